// round 15
// baseline (speedup 1.0000x reference)
#include <cuda_runtime.h>
#include <cuda_bf16.h>
#include <mma.h>
#include <math.h>
#include <stdint.h>
#include <stddef.h>

using namespace nvcuda;

// Problem dims (fixed by the dataset)
#define NS   4096      // batch
#define TS   64        // timesteps
#define FI   32        // input features
#define HD   128       // hidden
#define GD   384       // 3*H
#define NK   20        // top-k
#define SLOPE_F 0.2f
#define GRROWS 28      // batch rows per GRU CTA (147 CTAs -> all 148 SMs)

typedef unsigned long long ull;
typedef __nv_bfloat16 bf16;

// ---------------- f32x2 packed helpers (Blackwell FFMA2) --------------------
__device__ __forceinline__ ull pack2(float lo, float hi) {
    ull r;
    asm("mov.b64 %0, {%1, %2};" : "=l"(r) : "f"(lo), "f"(hi));
    return r;
}
__device__ __forceinline__ float2 unpack2(ull v) {
    float2 r;
    asm("mov.b64 {%0, %1}, %2;" : "=f"(r.x), "=f"(r.y) : "l"(v));
    return r;
}
__device__ __forceinline__ void ffma2(ull& d, ull a, ull b) {
    asm("fma.rn.f32x2 %0, %1, %2, %0;" : "+l"(d) : "l"(a), "l"(b));
}

// ---------------- scratch (device globals; no runtime allocation) ----------
__device__ float d_gi[(size_t)NS * TS * GD];
__device__ float d_h0[(size_t)NS * TS * HD];
__device__ float d_g  [NS * HD];
__device__ float d_gn [NS * HD];
__device__ float d_sim[(size_t)NS * NS];
__device__ int   d_tidx[NS * NK];
__device__ float d_tval[NS * NK];
__device__ float d_colsum[NS];
__device__ float d_colZ[NS];
__device__ float d_valid[NS];
__device__ float d_concept[NS * HD];
__device__ float d_cf [NS * HD];
__device__ float d_cfn[NS * HD];
__device__ float d_hsb[NS * HD];
__device__ float d_t1 [NS * HD];
__device__ float d_t2 [NS * HD];
__device__ float d_t3 [NS * HD];
__device__ float d_t4 [NS * HD];
__device__ bf16 d_W0hi[GD * FI];    // Wih0 split
__device__ bf16 d_W0lo[GD * FI];
__device__ bf16 d_Whi[GD * HD];     // Wih1 split
__device__ bf16 d_Wlo[GD * HD];
__device__ bf16 d_gnhi[NS * HD];
__device__ bf16 d_gnlo[NS * HD];
__device__ bf16 d_cfnhi[NS * HD];
__device__ bf16 d_cfnlo[NS * HD];
__device__ bf16 d_cf2hi[NS * HD];
__device__ bf16 d_cf2lo[NS * HD];

// ---------------- fp32 GEMM: 64x64 tile (NS x 128 x 128 head GEMMs) ---------
template<bool ACT, bool SUBPRE>
__global__ __launch_bounds__(256) void k_gemm64(
    const float* __restrict__ A, const float* __restrict__ B,
    const float* __restrict__ bias, const float* __restrict__ rs,
    const float* __restrict__ pre, float* __restrict__ C,
    int M, int N, int K)
{
    __shared__ alignas(16) float As[16][68];
    __shared__ alignas(16) float Bs[16][68];
    const int bm = blockIdx.y * 64, bn = blockIdx.x * 64;
    const int tid = threadIdx.x;
    const int a_m = tid >> 2, a_k = (tid & 3) * 4;
    const int ty = tid >> 4, tx = tid & 15;
    const int m0 = ty * 4, n0 = tx * 4;

    ull acc2[2][4];
    #pragma unroll
    for (int p = 0; p < 2; p++)
        #pragma unroll
        for (int j = 0; j < 4; j++) acc2[p][j] = 0ull;

    float4 ra, rb;
    ra = *(const float4*)(A + (size_t)(bm + a_m) * K + a_k);
    rb = *(const float4*)(B + (size_t)(bn + a_m) * K + a_k);

    for (int k0 = 0; k0 < K; k0 += 16) {
        As[a_k + 0][a_m] = ra.x; As[a_k + 1][a_m] = ra.y;
        As[a_k + 2][a_m] = ra.z; As[a_k + 3][a_m] = ra.w;
        Bs[a_k + 0][a_m] = rb.x; Bs[a_k + 1][a_m] = rb.y;
        Bs[a_k + 2][a_m] = rb.z; Bs[a_k + 3][a_m] = rb.w;
        __syncthreads();
        if (k0 + 16 < K) {
            ra = *(const float4*)(A + (size_t)(bm + a_m) * K + k0 + 16 + a_k);
            rb = *(const float4*)(B + (size_t)(bn + a_m) * K + k0 + 16 + a_k);
        }
        #pragma unroll
        for (int kk = 0; kk < 16; kk++) {
            ulonglong2 aP = *(const ulonglong2*)&As[kk][m0];
            float4 b = *(const float4*)&Bs[kk][n0];
            ull bd0 = pack2(b.x, b.x), bd1 = pack2(b.y, b.y);
            ull bd2 = pack2(b.z, b.z), bd3 = pack2(b.w, b.w);
            ffma2(acc2[0][0], aP.x, bd0); ffma2(acc2[0][1], aP.x, bd1);
            ffma2(acc2[0][2], aP.x, bd2); ffma2(acc2[0][3], aP.x, bd3);
            ffma2(acc2[1][0], aP.y, bd0); ffma2(acc2[1][1], aP.y, bd1);
            ffma2(acc2[1][2], aP.y, bd2); ffma2(acc2[1][3], aP.y, bd3);
        }
        __syncthreads();
    }

    #pragma unroll
    for (int p = 0; p < 2; p++) {
        int rowA = bm + m0 + 2 * p;
        int rowB = rowA + 1;
        float rsA = rs ? rs[rowA] : 1.f;
        float rsB = rs ? rs[rowB] : 1.f;
        float va[4], vb[4];
        #pragma unroll
        for (int j = 0; j < 4; j++) {
            float2 v = unpack2(acc2[p][j]);
            float a = v.x, b = v.y;
            if (bias) { float bj = bias[bn + n0 + j]; a += bj; b += bj; }
            if (ACT) {
                a = a > 0.f ? a : SLOPE_F * a;
                b = b > 0.f ? b : SLOPE_F * b;
            }
            a *= rsA; b *= rsB;
            if (SUBPRE) {
                a = pre[(size_t)rowA * N + bn + n0 + j] - a;
                b = pre[(size_t)rowB * N + bn + n0 + j] - b;
            }
            va[j] = a; vb[j] = b;
        }
        *(float4*)(C + (size_t)rowA * N + bn + n0) =
            make_float4(va[0], va[1], va[2], va[3]);
        *(float4*)(C + (size_t)rowB * N + bn + n0) =
            make_float4(vb[0], vb[1], vb[2], vb[3]);
    }
}

// ---------------- dual fp32 GEMM: fore + back from shared A (hs) ------------
__global__ __launch_bounds__(256) void k_gemm64_dual(
    const float* __restrict__ A,
    const float* __restrict__ Wf, const float* __restrict__ bfv,
    const float* __restrict__ Wb, const float* __restrict__ bbv,
    const float* __restrict__ pre,
    float* __restrict__ Cf, float* __restrict__ Cb,
    int M, int N, int K)
{
    __shared__ alignas(16) float As[16][68];
    __shared__ alignas(16) float BsF[16][68];
    __shared__ alignas(16) float BsB[16][68];
    const int bm = blockIdx.y * 64, bn = blockIdx.x * 64;
    const int tid = threadIdx.x;
    const int a_m = tid >> 2, a_k = (tid & 3) * 4;
    const int ty = tid >> 4, tx = tid & 15;
    const int m0 = ty * 4, n0 = tx * 4;

    ull accF[2][4], accB[2][4];
    #pragma unroll
    for (int p = 0; p < 2; p++)
        #pragma unroll
        for (int j = 0; j < 4; j++) { accF[p][j] = 0ull; accB[p][j] = 0ull; }

    float4 ra, rbf, rbb;
    ra  = *(const float4*)(A  + (size_t)(bm + a_m) * K + a_k);
    rbf = *(const float4*)(Wf + (size_t)(bn + a_m) * K + a_k);
    rbb = *(const float4*)(Wb + (size_t)(bn + a_m) * K + a_k);

    for (int k0 = 0; k0 < K; k0 += 16) {
        As[a_k + 0][a_m] = ra.x; As[a_k + 1][a_m] = ra.y;
        As[a_k + 2][a_m] = ra.z; As[a_k + 3][a_m] = ra.w;
        BsF[a_k + 0][a_m] = rbf.x; BsF[a_k + 1][a_m] = rbf.y;
        BsF[a_k + 2][a_m] = rbf.z; BsF[a_k + 3][a_m] = rbf.w;
        BsB[a_k + 0][a_m] = rbb.x; BsB[a_k + 1][a_m] = rbb.y;
        BsB[a_k + 2][a_m] = rbb.z; BsB[a_k + 3][a_m] = rbb.w;
        __syncthreads();
        if (k0 + 16 < K) {
            ra  = *(const float4*)(A  + (size_t)(bm + a_m) * K + k0 + 16 + a_k);
            rbf = *(const float4*)(Wf + (size_t)(bn + a_m) * K + k0 + 16 + a_k);
            rbb = *(const float4*)(Wb + (size_t)(bn + a_m) * K + k0 + 16 + a_k);
        }
        #pragma unroll
        for (int kk = 0; kk < 16; kk++) {
            ulonglong2 aP = *(const ulonglong2*)&As[kk][m0];
            float4 bf = *(const float4*)&BsF[kk][n0];
            float4 bb = *(const float4*)&BsB[kk][n0];
            ull f0 = pack2(bf.x, bf.x), f1 = pack2(bf.y, bf.y);
            ull f2 = pack2(bf.z, bf.z), f3 = pack2(bf.w, bf.w);
            ull g0 = pack2(bb.x, bb.x), g1 = pack2(bb.y, bb.y);
            ull g2 = pack2(bb.z, bb.z), g3 = pack2(bb.w, bb.w);
            ffma2(accF[0][0], aP.x, f0); ffma2(accF[0][1], aP.x, f1);
            ffma2(accF[0][2], aP.x, f2); ffma2(accF[0][3], aP.x, f3);
            ffma2(accF[1][0], aP.y, f0); ffma2(accF[1][1], aP.y, f1);
            ffma2(accF[1][2], aP.y, f2); ffma2(accF[1][3], aP.y, f3);
            ffma2(accB[0][0], aP.x, g0); ffma2(accB[0][1], aP.x, g1);
            ffma2(accB[0][2], aP.x, g2); ffma2(accB[0][3], aP.x, g3);
            ffma2(accB[1][0], aP.y, g0); ffma2(accB[1][1], aP.y, g1);
            ffma2(accB[1][2], aP.y, g2); ffma2(accB[1][3], aP.y, g3);
        }
        __syncthreads();
    }

    #pragma unroll
    for (int p = 0; p < 2; p++) {
        int rowA = bm + m0 + 2 * p;
        int rowB = rowA + 1;
        float vfA[4], vfB[4], vbA[4], vbB[4];
        #pragma unroll
        for (int j = 0; j < 4; j++) {
            float2 vf = unpack2(accF[p][j]);
            float2 vb = unpack2(accB[p][j]);
            float fa = vf.x + bfv[bn + n0 + j];
            float fb = vf.y + bfv[bn + n0 + j];
            float ba = vb.x + bbv[bn + n0 + j];
            float bb2 = vb.y + bbv[bn + n0 + j];
            fa = fa > 0.f ? fa : SLOPE_F * fa;
            fb = fb > 0.f ? fb : SLOPE_F * fb;
            ba = ba > 0.f ? ba : SLOPE_F * ba;
            bb2 = bb2 > 0.f ? bb2 : SLOPE_F * bb2;
            vfA[j] = fa; vfB[j] = fb;
            vbA[j] = pre[(size_t)rowA * N + bn + n0 + j] - ba;
            vbB[j] = pre[(size_t)rowB * N + bn + n0 + j] - bb2;
        }
        *(float4*)(Cf + (size_t)rowA * N + bn + n0) =
            make_float4(vfA[0], vfA[1], vfA[2], vfA[3]);
        *(float4*)(Cf + (size_t)rowB * N + bn + n0) =
            make_float4(vfB[0], vfB[1], vfB[2], vfB[3]);
        *(float4*)(Cb + (size_t)rowA * N + bn + n0) =
            make_float4(vbA[0], vbA[1], vbA[2], vbA[3]);
        *(float4*)(Cb + (size_t)rowB * N + bn + n0) =
            make_float4(vbB[0], vbB[1], vbB[2], vbB[3]);
    }
}

// reduce over split-K partial slices: C = sum_z P[z]
__global__ void k_reduce(const float* __restrict__ P, float* __restrict__ C,
                         int nslice, int total4)
{
    int i = blockIdx.x * blockDim.x + threadIdx.x;
    if (i >= total4) return;
    size_t b = (size_t)i * 4;
    float4 s = make_float4(0.f, 0.f, 0.f, 0.f);
    for (int z = 0; z < nslice; z++) {
        float4 v = *(const float4*)(P + (size_t)z * total4 * 4 + b);
        s.x += v.x; s.y += v.y; s.z += v.z; s.w += v.w;
    }
    *(float4*)(C + b) = s;
}

// ---------------- bf16 hi/lo split of TWO weight matrices (one launch) ------
__global__ void k_wsplit2(const float* __restrict__ W0,
                          bf16* __restrict__ h0, bf16* __restrict__ l0, int n0,
                          const float* __restrict__ W1,
                          bf16* __restrict__ h1, bf16* __restrict__ l1, int n1)
{
    int i = blockIdx.x * 256 + threadIdx.x;
    if (i < n0) {
        float v = W0[i];
        bf16 h = __float2bfloat16(v);
        h0[i] = h;
        l0[i] = __float2bfloat16(v - __bfloat162float(h));
    } else if (i < n0 + n1) {
        int j = i - n0;
        float v = W1[j];
        bf16 h = __float2bfloat16(v);
        h1[j] = h;
        l1[j] = __float2bfloat16(v - __bfloat162float(h));
    }
}

// ---------------- generic wmma bf16x3:  C = A @ B^T (runtime K) --------------
template<bool EXPCS>
__global__ __launch_bounds__(256) void k_wmma_nt(
    const float* __restrict__ A,
    const bf16* __restrict__ Bhi, const bf16* __restrict__ Blo,
    float* __restrict__ colZacc, float* __restrict__ C, int N, int K)
{
    __shared__ alignas(32) bf16 Ahi[128][24];
    __shared__ alignas(32) bf16 Alo[128][24];
    __shared__ alignas(32) bf16 Bh[64][24];
    __shared__ alignas(32) bf16 Bl[64][24];
    __shared__ float colsh[64];
    __shared__ float stag[8][16][16];
    const int bm = blockIdx.y * 128, bn = blockIdx.x * 64;
    const int tid = threadIdx.x, wid = tid >> 5;
    const int lane = tid & 31;
    const int wm = (wid >> 1) * 32, wn = (wid & 1) * 32;

    if (EXPCS && tid < 64) colsh[tid] = 0.f;

    wmma::fragment<wmma::accumulator, 16, 16, 16, float> acc[2][2];
    #pragma unroll
    for (int i = 0; i < 2; i++)
        #pragma unroll
        for (int j = 0; j < 2; j++) wmma::fill_fragment(acc[i][j], 0.f);

    const int a_m = tid >> 1, a_k = (tid & 1) * 8;
    const int b_n = tid >> 2, b_k = (tid & 3) * 4;

    float4 v0, v1;
    uint2 rbh, rbl;
    {
        const float* Ap = A + (size_t)(bm + a_m) * K + a_k;
        v0 = *(const float4*)Ap;
        v1 = *(const float4*)(Ap + 4);
        rbh = *(const uint2*)(Bhi + (size_t)(bn + b_n) * K + b_k);
        rbl = *(const uint2*)(Blo + (size_t)(bn + b_n) * K + b_k);
    }

    for (int k0 = 0; k0 < K; k0 += 16) {
        float av[8] = {v0.x, v0.y, v0.z, v0.w, v1.x, v1.y, v1.z, v1.w};
        bf16 hb[8], lb[8];
        #pragma unroll
        for (int q = 0; q < 8; q++) {
            bf16 h = __float2bfloat16(av[q]);
            hb[q] = h;
            lb[q] = __float2bfloat16(av[q] - __bfloat162float(h));
        }
        *(uint4*)&Ahi[a_m][a_k] = *(uint4*)hb;
        *(uint4*)&Alo[a_m][a_k] = *(uint4*)lb;
        *(uint2*)&Bh[b_n][b_k] = rbh;
        *(uint2*)&Bl[b_n][b_k] = rbl;
        __syncthreads();
        if (k0 + 16 < K) {
            const float* Ap = A + (size_t)(bm + a_m) * K + (k0 + 16) + a_k;
            v0 = *(const float4*)Ap;
            v1 = *(const float4*)(Ap + 4);
            rbh = *(const uint2*)(Bhi + (size_t)(bn + b_n) * K + (k0 + 16) + b_k);
            rbl = *(const uint2*)(Blo + (size_t)(bn + b_n) * K + (k0 + 16) + b_k);
        }

        wmma::fragment<wmma::matrix_a, 16, 16, 16, bf16, wmma::row_major> af[2];
        wmma::fragment<wmma::matrix_b, 16, 16, 16, bf16, wmma::col_major> bfr[2];
        wmma::load_matrix_sync(af[0], &Ahi[wm][0], 24);
        wmma::load_matrix_sync(af[1], &Ahi[wm + 16][0], 24);
        wmma::load_matrix_sync(bfr[0], &Bh[wn][0], 24);
        wmma::load_matrix_sync(bfr[1], &Bh[wn + 16][0], 24);
        #pragma unroll
        for (int i = 0; i < 2; i++)
            #pragma unroll
            for (int j = 0; j < 2; j++)
                wmma::mma_sync(acc[i][j], af[i], bfr[j], acc[i][j]);
        wmma::load_matrix_sync(bfr[0], &Bl[wn][0], 24);
        wmma::load_matrix_sync(bfr[1], &Bl[wn + 16][0], 24);
        #pragma unroll
        for (int i = 0; i < 2; i++)
            #pragma unroll
            for (int j = 0; j < 2; j++)
                wmma::mma_sync(acc[i][j], af[i], bfr[j], acc[i][j]);
        wmma::load_matrix_sync(af[0], &Alo[wm][0], 24);
        wmma::load_matrix_sync(af[1], &Alo[wm + 16][0], 24);
        wmma::load_matrix_sync(bfr[0], &Bh[wn][0], 24);
        wmma::load_matrix_sync(bfr[1], &Bh[wn + 16][0], 24);
        #pragma unroll
        for (int i = 0; i < 2; i++)
            #pragma unroll
            for (int j = 0; j < 2; j++)
                wmma::mma_sync(acc[i][j], af[i], bfr[j], acc[i][j]);
        __syncthreads();
    }

    #pragma unroll
    for (int i = 0; i < 2; i++)
        #pragma unroll
        for (int j = 0; j < 2; j++) {
            if (EXPCS) {
                #pragma unroll
                for (int e = 0; e < acc[i][j].num_elements; e++)
                    acc[i][j].x[e] = __expf(acc[i][j].x[e]);
                wmma::store_matrix_sync(&stag[wid][0][0], acc[i][j], 16,
                                        wmma::mem_row_major);
                __syncwarp();
                if (lane < 16) {
                    float s = 0.f;
                    #pragma unroll
                    for (int r = 0; r < 16; r++) s += stag[wid][r][lane];
                    atomicAdd(&colsh[wn + 16 * j + lane], s);
                }
                __syncwarp();
            }
            wmma::store_matrix_sync(
                C + (size_t)(bm + wm + 16 * i) * N + bn + wn + 16 * j,
                acc[i][j], N, wmma::mem_row_major);
        }

    if (EXPCS) {
        __syncthreads();
        if (tid < 64) atomicAdd(&colZacc[bn + tid], colsh[tid]);
    }
}

// ---------------- wmma bf16x3:  P[z] = A[:, kslice] @ B[kslice, :] -----------
__global__ __launch_bounds__(256) void k_wmma_nn(
    const float* __restrict__ A,
    const bf16* __restrict__ Bhi, const bf16* __restrict__ Blo,
    float* __restrict__ P, int M, int K, int ksplit)
{
    __shared__ alignas(32) bf16 Ahi[128][24];
    __shared__ alignas(32) bf16 Alo[128][24];
    __shared__ alignas(32) bf16 Bh[16][72];
    __shared__ alignas(32) bf16 Bl[16][72];
    const int bm = blockIdx.y * 128, bn = blockIdx.x * 64;
    const int tid = threadIdx.x, wid = tid >> 5;
    const int wm = (wid >> 1) * 32, wn = (wid & 1) * 32;
    const int kbase = blockIdx.z * ksplit;
    const int kend = kbase + ksplit;

    wmma::fragment<wmma::accumulator, 16, 16, 16, float> acc[2][2];
    #pragma unroll
    for (int i = 0; i < 2; i++)
        #pragma unroll
        for (int j = 0; j < 2; j++) wmma::fill_fragment(acc[i][j], 0.f);

    const int a_m = tid >> 1, a_k = (tid & 1) * 8;
    const int bk_r = tid >> 4, bn_c = (tid & 15) * 4;

    float4 v0, v1;
    uint2 rbh, rbl;
    {
        const float* Ap = A + (size_t)(bm + a_m) * K + kbase + a_k;
        v0 = *(const float4*)Ap;
        v1 = *(const float4*)(Ap + 4);
        rbh = *(const uint2*)(Bhi + (size_t)(kbase + bk_r) * HD + bn + bn_c);
        rbl = *(const uint2*)(Blo + (size_t)(kbase + bk_r) * HD + bn + bn_c);
    }

    for (int k0 = kbase; k0 < kend; k0 += 16) {
        float av[8] = {v0.x, v0.y, v0.z, v0.w, v1.x, v1.y, v1.z, v1.w};
        bf16 hb[8], lb[8];
        #pragma unroll
        for (int q = 0; q < 8; q++) {
            bf16 h = __float2bfloat16(av[q]);
            hb[q] = h;
            lb[q] = __float2bfloat16(av[q] - __bfloat162float(h));
        }
        *(uint4*)&Ahi[a_m][a_k] = *(uint4*)hb;
        *(uint4*)&Alo[a_m][a_k] = *(uint4*)lb;
        *(uint2*)&Bh[bk_r][bn_c] = rbh;
        *(uint2*)&Bl[bk_r][bn_c] = rbl;
        __syncthreads();
        if (k0 + 16 < kend) {
            const float* Ap = A + (size_t)(bm + a_m) * K + (k0 + 16) + a_k;
            v0 = *(const float4*)Ap;
            v1 = *(const float4*)(Ap + 4);
            rbh = *(const uint2*)(Bhi + (size_t)(k0 + 16 + bk_r) * HD + bn + bn_c);
            rbl = *(const uint2*)(Blo + (size_t)(k0 + 16 + bk_r) * HD + bn + bn_c);
        }

        wmma::fragment<wmma::matrix_a, 16, 16, 16, bf16, wmma::row_major> af[2];
        wmma::fragment<wmma::matrix_b, 16, 16, 16, bf16, wmma::row_major> bfr[2];
        wmma::load_matrix_sync(af[0], &Ahi[wm][0], 24);
        wmma::load_matrix_sync(af[1], &Ahi[wm + 16][0], 24);
        wmma::load_matrix_sync(bfr[0], &Bh[0][wn], 72);
        wmma::load_matrix_sync(bfr[1], &Bh[0][wn + 16], 72);
        #pragma unroll
        for (int i = 0; i < 2; i++)
            #pragma unroll
            for (int j = 0; j < 2; j++)
                wmma::mma_sync(acc[i][j], af[i], bfr[j], acc[i][j]);
        wmma::load_matrix_sync(bfr[0], &Bl[0][wn], 72);
        wmma::load_matrix_sync(bfr[1], &Bl[0][wn + 16], 72);
        #pragma unroll
        for (int i = 0; i < 2; i++)
            #pragma unroll
            for (int j = 0; j < 2; j++)
                wmma::mma_sync(acc[i][j], af[i], bfr[j], acc[i][j]);
        wmma::load_matrix_sync(af[0], &Alo[wm][0], 24);
        wmma::load_matrix_sync(af[1], &Alo[wm + 16][0], 24);
        wmma::load_matrix_sync(bfr[0], &Bh[0][wn], 72);
        wmma::load_matrix_sync(bfr[1], &Bh[0][wn + 16], 72);
        #pragma unroll
        for (int i = 0; i < 2; i++)
            #pragma unroll
            for (int j = 0; j < 2; j++)
                wmma::mma_sync(acc[i][j], af[i], bfr[j], acc[i][j]);
        __syncthreads();
    }

    float* Pw = P + (size_t)blockIdx.z * ((size_t)M * HD);
    #pragma unroll
    for (int i = 0; i < 2; i++)
        #pragma unroll
        for (int j = 0; j < 2; j++)
            wmma::store_matrix_sync(
                Pw + (size_t)(bm + wm + 16 * i) * HD + bn + wn + 16 * j,
                acc[i][j], HD, wmma::mem_row_major);
}

// ---------------- persistent GRU recurrent kernel: 768 thr ------------------
// Mapping (2 outputs, quarter-k): o = tid%192 -> outputs o, o+192;
// q = tid/192 -> k in [32q, 32q+32). wq = 64 floats (fits 85-reg cap).
// Each h-quarter LDS.128 feeds 2 outputs (same wavefront count as the
// 384-thread layout) but 24 warps/SM hide the latency. 4 partial buffers.
// gi is read directly from GMEM in the gate phase (no SMEM staging).
template<bool WRITE_SEQ>
__global__ __launch_bounds__(768, 1) void k_gru(
    const float* __restrict__ gi, const float* __restrict__ Whh,
    const float* __restrict__ bhh, const float* __restrict__ bih,
    float* __restrict__ hout)
{
    extern __shared__ float sm[];
    float* h_sh = sm;                             // GRROWS*128
    float* ghQ  = sm + GRROWS * HD;               // 4 * GRROWS*384
    __shared__ float bih_sh[GD];
    const int tid = threadIdx.x;
    const int o = tid % 192;
    const int q = tid / 192;                      // 0..3
    const int o2 = o + 192;
    const int base = blockIdx.x * GRROWS;
    const int rows = (NS - base < GRROWS) ? (NS - base) : GRROWS;
    float* ghOut = ghQ + (size_t)q * GRROWS * GD;

    // weights: rows o and o+192, k in [32q, 32q+32): 16+16 packed pairs
    ull wq[32];
    {
        const ulonglong2* wg0 =
            (const ulonglong2*)(Whh + (size_t)o * HD + q * 32);
        const ulonglong2* wg1 =
            (const ulonglong2*)(Whh + (size_t)o2 * HD + q * 32);
        #pragma unroll
        for (int i = 0; i < 8; i++) {
            ulonglong2 t0 = wg0[i];
            wq[2 * i] = t0.x; wq[2 * i + 1] = t0.y;
        }
        #pragma unroll
        for (int i = 0; i < 8; i++) {
            ulonglong2 t1 = wg1[i];
            wq[16 + 2 * i] = t1.x; wq[16 + 2 * i + 1] = t1.y;
        }
    }
    const float bo0 = (q == 0) ? bhh[o]  : 0.f;
    const float bo1 = (q == 0) ? bhh[o2] : 0.f;
    if (tid < GD) bih_sh[tid] = bih[tid];
    for (int idx = tid; idx < rows * HD; idx += 768) h_sh[idx] = 0.f;
    __syncthreads();

    for (int t = 0; t < TS; t++) {
        // partial matvec: TWO rows per iteration, 4 independent chains
        #pragma unroll 1
        for (int r = 0; r < rows; r += 2) {
            const ulonglong2* hp0 =
                (const ulonglong2*)(h_sh + r * HD + q * 32);
            const ulonglong2* hp1 =
                (const ulonglong2*)(h_sh + (r + 1) * HD + q * 32);
            ull a0 = 0ull, b0 = 0ull, a1 = 0ull, b1 = 0ull;
            #pragma unroll
            for (int i = 0; i < 8; i++) {
                ulonglong2 x0 = hp0[i];
                ulonglong2 x1 = hp1[i];
                ffma2(a0, x0.x, wq[2 * i]);
                ffma2(b0, x0.x, wq[16 + 2 * i]);
                ffma2(a1, x1.x, wq[2 * i]);
                ffma2(b1, x1.x, wq[16 + 2 * i]);
                ffma2(a0, x0.y, wq[2 * i + 1]);
                ffma2(b0, x0.y, wq[16 + 2 * i + 1]);
                ffma2(a1, x1.y, wq[2 * i + 1]);
                ffma2(b1, x1.y, wq[16 + 2 * i + 1]);
            }
            float2 pa0 = unpack2(a0), pb0 = unpack2(b0);
            float2 pa1 = unpack2(a1), pb1 = unpack2(b1);
            ghOut[r * GD + o]        = (pa0.x + pa0.y) + bo0;
            ghOut[r * GD + o2]       = (pb0.x + pb0.y) + bo1;
            ghOut[(r + 1) * GD + o]  = (pa1.x + pa1.y) + bo0;
            ghOut[(r + 1) * GD + o2] = (pb1.x + pb1.y) + bo1;
        }
        __syncthreads();
        // gate update (sum 4 partials; gi read from GMEM, coalesced)
        #pragma unroll 1
        for (int idx = tid; idx < rows * HD; idx += 768) {
            int r = idx >> 7, j = idx & 127;
            size_t gb = ((size_t)(base + r) * TS + t) * GD + j;
            float gir = __ldg(gi + gb)       + bih_sh[j];
            float giz = __ldg(gi + gb + 128) + bih_sh[j + 128];
            float gin = __ldg(gi + gb + 256) + bih_sh[j + 256];
            float ghr = 0.f, ghz = 0.f, ghn = 0.f;
            #pragma unroll
            for (int p = 0; p < 4; p++) {
                const float* gp = ghQ + (size_t)p * GRROWS * GD + r * GD;
                ghr += gp[j];
                ghz += gp[j + 128];
                ghn += gp[j + 256];
            }
            float rg = __fdividef(1.f, 1.f + __expf(-(gir + ghr)));
            float zg = __fdividef(1.f, 1.f + __expf(-(giz + ghz)));
            float a2 = gin + rg * ghn;
            float ng = 1.f - __fdividef(2.f, __expf(2.f * a2) + 1.f);
            float hprev = h_sh[idx];
            float hn = (1.f - zg) * ng + zg * hprev;
            h_sh[idx] = hn;
            if (WRITE_SEQ)
                hout[((size_t)(base + r) * TS + t) * HD + j] = hn;
            else if (t == TS - 1)
                hout[(size_t)(base + r) * HD + j] = hn;
        }
        __syncthreads();
    }
}

// ---------------- small helpers --------------------------------------------
__global__ void k_zero(float* p, int n) {
    int i = blockIdx.x * blockDim.x + threadIdx.x;
    if (i < n) p[i] = 0.f;
}

// row L2-normalize; also emit bf16 hi/lo split of the normalized row
__global__ void k_rownorm(const float* __restrict__ src, float* __restrict__ dst,
                          bf16* __restrict__ hi, bf16* __restrict__ lo)
{
    int row = blockIdx.x * 8 + (threadIdx.x >> 5);
    int lane = threadIdx.x & 31;
    const float4* s4 = (const float4*)(src + (size_t)row * HD);
    float4 v = s4[lane];
    float ss = v.x*v.x + v.y*v.y + v.z*v.z + v.w*v.w;
    #pragma unroll
    for (int off = 16; off; off >>= 1) ss += __shfl_xor_sync(0xffffffffu, ss, off);
    float n = sqrtf(ss);
    float inv = (n > 0.f) ? 1.f / n : 0.f;
    float4 r = make_float4(v.x*inv, v.y*inv, v.z*inv, v.w*inv);
    ((float4*)(dst + (size_t)row * HD))[lane] = r;
    float rv[4] = {r.x, r.y, r.z, r.w};
    bf16 hb[4], lb[4];
    #pragma unroll
    for (int q = 0; q < 4; q++) {
        bf16 h = __float2bfloat16(rv[q]);
        hb[q] = h;
        lb[q] = __float2bfloat16(rv[q] - __bfloat162float(h));
    }
    *(uint2*)(hi + (size_t)row * HD + lane * 4) = *(uint2*)hb;
    *(uint2*)(lo + (size_t)row * HD + lane * 4) = *(uint2*)lb;
}

// cf2 = cf / colZ (row-wise), emitted as bf16 hi/lo
__global__ void k_cfscale(const float* __restrict__ cf,
                          const float* __restrict__ colZ,
                          bf16* __restrict__ hi, bf16* __restrict__ lo)
{
    int row = blockIdx.x * 8 + (threadIdx.x >> 5);
    int lane = threadIdx.x & 31;
    float rz = __fdividef(1.f, colZ[row]);
    float4 v = ((const float4*)(cf + (size_t)row * HD))[lane];
    float rv[4] = {v.x * rz, v.y * rz, v.z * rz, v.w * rz};
    bf16 hb[4], lb[4];
    #pragma unroll
    for (int q = 0; q < 4; q++) {
        bf16 h = __float2bfloat16(rv[q]);
        hb[q] = h;
        lb[q] = __float2bfloat16(rv[q] - __bfloat162float(h));
    }
    *(uint2*)(hi + (size_t)row * HD + lane * 4) = *(uint2*)hb;
    *(uint2*)(lo + (size_t)row * HD + lane * 4) = *(uint2*)lb;
}

// top-K=20 per row of |sim| (diag excluded), jax-stable ties (lowest index).
__global__ __launch_bounds__(256) void k_topk(
    const float* __restrict__ sim, int* __restrict__ tidx,
    float* __restrict__ tval, float* __restrict__ colsum)
{
    int i = blockIdx.x;
    __shared__ float sabs[NS];
    __shared__ float segv[128];
    __shared__ int   segi[128];
    __shared__ float bcv[4];
    __shared__ int   bci[4];
    const int tid = threadIdx.x;
    const float* row = sim + (size_t)i * NS;

    for (int c4 = tid; c4 < NS / 4; c4 += 256) {
        float4 v = *(const float4*)(row + c4 * 4);
        float4 a = make_float4(fabsf(v.x), fabsf(v.y), fabsf(v.z), fabsf(v.w));
        *(float4*)&sabs[c4 * 4] = a;
    }
    __syncthreads();
    if (tid == 0) sabs[i] = -1.f;
    __syncthreads();

    if (tid < 128) {
        float bv = -2.f; int bi = tid * 32;
        #pragma unroll 4
        for (int j = 0; j < 32; j++) {
            float v = sabs[tid * 32 + j];
            if (v > bv) { bv = v; bi = tid * 32 + j; }
        }
        segv[tid] = bv; segi[tid] = bi;
    }
    __syncthreads();

    for (int k = 0; k < NK; k++) {
        if (tid < 128) {
            float bv = segv[tid]; int bi = segi[tid];
            #pragma unroll
            for (int off = 16; off; off >>= 1) {
                float ov = __shfl_down_sync(0xffffffffu, bv, off);
                int   oi = __shfl_down_sync(0xffffffffu, bi, off);
                if (ov > bv || (ov == bv && oi < bi)) { bv = ov; bi = oi; }
            }
            if ((tid & 31) == 0) { bcv[tid >> 5] = bv; bci[tid >> 5] = bi; }
        }
        __syncthreads();
        if (tid < 32) {
            int bi = 0;
            if (tid == 0) {
                float bv = bcv[0]; bi = bci[0];
                #pragma unroll
                for (int w = 1; w < 4; w++)
                    if (bcv[w] > bv || (bcv[w] == bv && bci[w] < bi)) {
                        bv = bcv[w]; bi = bci[w];
                    }
                tidx[i * NK + k] = bi;
                float sv = row[bi];
                tval[i * NK + k] = sv;
                atomicAdd(&colsum[bi], sv);
                sabs[bi] = -2.f;
            }
            bi = __shfl_sync(0xffffffffu, bi, 0);
            __syncwarp();
            int s = bi >> 5;
            int idx = s * 32 + tid;
            float bv2 = sabs[idx]; int bi2 = idx;
            #pragma unroll
            for (int off = 16; off; off >>= 1) {
                float ov = __shfl_down_sync(0xffffffffu, bv2, off);
                int   oi = __shfl_down_sync(0xffffffffu, bi2, off);
                if (ov > bv2 || (ov == bv2 && oi < bi2)) { bv2 = ov; bi2 = oi; }
            }
            if (tid == 0) { segv[s] = bv2; segi[s] = bi2; }
        }
        __syncthreads();
    }
}

__global__ void k_scatter(const int* __restrict__ tidx, const float* __restrict__ tval,
                          const float* __restrict__ g, float* __restrict__ concept)
{
    int i = blockIdx.x, d = threadIdx.x;
    float gv = g[(size_t)i * HD + d];
    #pragma unroll
    for (int k = 0; k < NK; k++) {
        int c = __ldg(&tidx[i * NK + k]);
        float v = __ldg(&tval[i * NK + k]);
        atomicAdd(&concept[(size_t)c * HD + d], v * gv);
    }
}

__global__ void k_diag_valid(const float* __restrict__ colsum, const float* __restrict__ sim,
                             const float* __restrict__ g, float* __restrict__ concept,
                             float* __restrict__ valid)
{
    int j = blockIdx.x, t = threadIdx.x;
    float cs = colsum[j];
    float v = concept[(size_t)j * HD + t];
    if (cs != 0.f) {
        float dg = sim[(size_t)j * NS + j];
        v += dg * g[(size_t)j * HD + t];
        concept[(size_t)j * HD + t] = v;
    }
    float s = v;
    #pragma unroll
    for (int off = 16; off; off >>= 1) s += __shfl_xor_sync(0xffffffffu, s, off);
    __shared__ float ws[4];
    if ((t & 31) == 0) ws[t >> 5] = s;
    __syncthreads();
    if (t == 0) {
        float tot = ws[0] + ws[1] + ws[2] + ws[3];
        valid[j] = (tot != 0.f) ? 1.f : 0.f;
    }
}

__global__ void k_final(const float* __restrict__ fore, const float* __restrict__ indi,
                        const float* __restrict__ Wout, const float* __restrict__ bout,
                        float* __restrict__ out)
{
    int row = blockIdx.x * 8 + (threadIdx.x >> 5);
    int lane = threadIdx.x & 31;
    float4 a = ((const float4*)(fore + (size_t)row * HD))[lane];
    float4 b = ((const float4*)(indi + (size_t)row * HD))[lane];
    float4 w = ((const float4*)Wout)[lane];
    float s = (a.x+b.x)*w.x + (a.y+b.y)*w.y + (a.z+b.z)*w.z + (a.w+b.w)*w.w;
    #pragma unroll
    for (int off = 16; off; off >>= 1) s += __shfl_xor_sync(0xffffffffu, s, off);
    if (lane == 0) out[row] = s + bout[0];
}

// ---------------- driver -----------------------------------------------------
extern "C" void kernel_launch(void* const* d_in, const int* in_sizes, int n_in,
                              void* d_out, int out_size)
{
    const float* x     = (const float*)d_in[0];
    const float* Wih0  = (const float*)d_in[1];
    const float* Whh0  = (const float*)d_in[2];
    const float* bih0  = (const float*)d_in[3];
    const float* bhh0  = (const float*)d_in[4];
    const float* Wih1  = (const float*)d_in[5];
    const float* Whh1  = (const float*)d_in[6];
    const float* bih1  = (const float*)d_in[7];
    const float* bhh1  = (const float*)d_in[8];
    const float* W_hc  = (const float*)d_in[9];
    const float* b_hc  = (const float*)d_in[10];
    const float* W_hs  = (const float*)d_in[11];
    const float* b_hs  = (const float*)d_in[12];
    const float* W_fore= (const float*)d_in[13];
    const float* b_fore= (const float*)d_in[14];
    const float* W_back= (const float*)d_in[15];
    const float* b_back= (const float*)d_in[16];
    const float* W_indi= (const float*)d_in[17];
    const float* b_indi= (const float*)d_in[18];
    const float* W_out = (const float*)d_in[19];
    const float* b_out = (const float*)d_in[20];
    float* out = (float*)d_out;

    float *gi, *h0, *g, *gn, *sim, *colsum, *colZ, *valid, *concept;
    float *cf, *cfn, *hs, *t1, *t2, *t3, *t4, *tval;
    int* tidx;
    bf16 *w0hi, *w0lo, *whi, *wlo, *gnhi, *gnlo, *cfnhi, *cfnlo, *cf2hi, *cf2lo;
    cudaGetSymbolAddress((void**)&gi,      d_gi);
    cudaGetSymbolAddress((void**)&h0,      d_h0);
    cudaGetSymbolAddress((void**)&g,       d_g);
    cudaGetSymbolAddress((void**)&gn,      d_gn);
    cudaGetSymbolAddress((void**)&sim,     d_sim);
    cudaGetSymbolAddress((void**)&tidx,    d_tidx);
    cudaGetSymbolAddress((void**)&tval,    d_tval);
    cudaGetSymbolAddress((void**)&colsum,  d_colsum);
    cudaGetSymbolAddress((void**)&colZ,    d_colZ);
    cudaGetSymbolAddress((void**)&valid,   d_valid);
    cudaGetSymbolAddress((void**)&concept, d_concept);
    cudaGetSymbolAddress((void**)&cf,      d_cf);
    cudaGetSymbolAddress((void**)&cfn,     d_cfn);
    cudaGetSymbolAddress((void**)&hs,      d_hsb);
    cudaGetSymbolAddress((void**)&t1,      d_t1);
    cudaGetSymbolAddress((void**)&t2,      d_t2);
    cudaGetSymbolAddress((void**)&t3,      d_t3);
    cudaGetSymbolAddress((void**)&t4,      d_t4);
    cudaGetSymbolAddress((void**)&w0hi,    d_W0hi);
    cudaGetSymbolAddress((void**)&w0lo,    d_W0lo);
    cudaGetSymbolAddress((void**)&whi,     d_Whi);
    cudaGetSymbolAddress((void**)&wlo,     d_Wlo);
    cudaGetSymbolAddress((void**)&gnhi,    d_gnhi);
    cudaGetSymbolAddress((void**)&gnlo,    d_gnlo);
    cudaGetSymbolAddress((void**)&cfnhi,   d_cfnhi);
    cudaGetSymbolAddress((void**)&cfnlo,   d_cfnlo);
    cudaGetSymbolAddress((void**)&cf2hi,   d_cf2hi);
    cudaGetSymbolAddress((void**)&cf2lo,   d_cf2lo);

    // h 28*128 + 4 partial buffers 4*28*384 floats = 186368 B
    const int GRU_SMEM = (GRROWS * HD + 4 * GRROWS * GD) * 4;
    cudaFuncSetAttribute((const void*)k_gru<true>,
                         cudaFuncAttributeMaxDynamicSharedMemorySize, GRU_SMEM);
    cudaFuncSetAttribute((const void*)k_gru<false>,
                         cudaFuncAttributeMaxDynamicSharedMemorySize, GRU_SMEM);

    const int MT = NS * TS;         // 262144
    const int GRU_GRID = (NS + GRROWS - 1) / GRROWS;  // 147

    // Launch order: gru0 is our 4th launch so ncu (-s 5 -c 1, one harness
    // pre-launch) captures the GRU kernel.
    // #1 split both input-weight matrices (one launch)
    k_wsplit2<<<(GD * FI + GD * HD + 255) / 256, 256>>>(
        Wih0, w0hi, w0lo, GD * FI, Wih1, whi, wlo, GD * HD);
    // #2 gi0 = x @ Wih0^T via wmma bf16x3 (K=32)
    k_wmma_nt<false><<<dim3(GD / 64, MT / 128), 256>>>(
        x, w0hi, w0lo, nullptr, gi, GD, FI);
    // #3 zero colsum
    k_zero<<<(NS + 255) / 256, 256>>>(colsum, NS);
    // #4 GRU layer 0 (writes full sequence)  <- ncu capture target
    k_gru<true><<<GRU_GRID, 768, GRU_SMEM>>>(gi, Whh0, bhh0, bih0, h0);
    // gi1 = h0 @ Wih1^T via wmma bf16x3 (K=128)
    k_wmma_nt<false><<<dim3(GD / 64, MT / 128), 256>>>(
        h0, whi, wlo, nullptr, gi, GD, HD);
    // GRU layer 1 (writes final hidden only -> g)
    k_gru<false><<<GRU_GRID, 768, GRU_SMEM>>>(gi, Whh1, bhh1, bih1, g);

    // zeros for later accumulators
    k_zero<<<(NS * HD + 255) / 256, 256>>>(concept, NS * HD);
    k_zero<<<(NS + 255) / 256, 256>>>(colZ, NS);

    // normalized g (fp32 + bf16 hi/lo); sim = gn @ gn^T via wmma bf16x3
    k_rownorm<<<NS / 8, 256>>>(g, gn, gnhi, gnlo);
    k_wmma_nt<false><<<dim3(NS / 64, NS / 128), 256>>>(
        gn, gnhi, gnlo, nullptr, sim, NS, HD);

    // top-K selection + concept aggregation
    k_topk<<<NS, 256>>>(sim, tidx, tval, colsum);
    k_scatter<<<NS, 128>>>(tidx, tval, g, concept);
    k_diag_valid<<<NS, 128>>>(colsum, sim, g, concept, valid);

    // cf = lrelu(concept @ W_hc^T + b_hc) * valid
    k_gemm64<true, false><<<dim3(HD / 64, NS / 64), 256>>>(
        concept, W_hc, b_hc, valid, nullptr, cf, NS, HD, HD);
    k_rownorm<<<NS / 8, 256>>>(cf, cfn, cfnhi, cfnlo);

    // E = exp(gn @ cfn^T) with fused column sums (wmma bf16x3)
    k_wmma_nt<true><<<dim3(NS / 64, NS / 128), 256>>>(
        gn, cfnhi, cfnlo, colZ, sim, NS, HD);

    // cf2 = cf / colZ (bf16 hi/lo); t1 = E @ cf2 (wmma, split-K=8) + reduce
    k_cfscale<<<NS / 8, 256>>>(cf, colZ, cf2hi, cf2lo);
    k_wmma_nn<<<dim3(HD / 64, NS / 128, 8), 256>>>(
        sim, cf2hi, cf2lo, gi, NS, NS, NS / 8);
    k_reduce<<<(NS * HD / 4 + 255) / 256, 256>>>(gi, t1, 8, NS * HD / 4);

    // hs = lrelu(t1 @ W_hs^T + b_hs)
    k_gemm64<true, false><<<dim3(HD / 64, NS / 64), 256>>>(
        t1, W_hs, b_hs, nullptr, nullptr, hs, NS, HD, HD);

    // fused: t2 = lrelu(hs@W_fore^T+b_fore); t3 = g - lrelu(hs@W_back^T+b_back)
    k_gemm64_dual<<<dim3(HD / 64, NS / 64), 256>>>(
        hs, W_fore, b_fore, W_back, b_back, g, t2, t3, NS, HD, HD);
    // t4 = lrelu(t3 @ W_indi^T + b_indi)
    k_gemm64<true, false><<<dim3(HD / 64, NS / 64), 256>>>(
        t3, W_indi, b_indi, nullptr, nullptr, t4, NS, HD, HD);
    k_final<<<NS / 8, 256>>>(t2, t4, W_out, b_out, out);
}

// round 16
// speedup vs baseline: 1.2305x; 1.2305x over previous
#include <cuda_runtime.h>
#include <cuda_bf16.h>
#include <mma.h>
#include <math.h>
#include <stdint.h>
#include <stddef.h>

using namespace nvcuda;

// Problem dims (fixed by the dataset)
#define NS   4096      // batch
#define TS   64        // timesteps
#define FI   32        // input features
#define HD   128       // hidden
#define GD   384       // 3*H
#define NK   20        // top-k
#define SLOPE_F 0.2f
#define GRROWS 28      // batch rows per GRU CTA (147 CTAs -> all 148 SMs)

typedef unsigned long long ull;
typedef __nv_bfloat16 bf16;

// ---------------- f32x2 packed helpers (Blackwell FFMA2) --------------------
__device__ __forceinline__ ull pack2(float lo, float hi) {
    ull r;
    asm("mov.b64 %0, {%1, %2};" : "=l"(r) : "f"(lo), "f"(hi));
    return r;
}
__device__ __forceinline__ float2 unpack2(ull v) {
    float2 r;
    asm("mov.b64 {%0, %1}, %2;" : "=f"(r.x), "=f"(r.y) : "l"(v));
    return r;
}
__device__ __forceinline__ void ffma2(ull& d, ull a, ull b) {
    asm("fma.rn.f32x2 %0, %1, %2, %0;" : "+l"(d) : "l"(a), "l"(b));
}

// ---------------- cp.async helpers -----------------------------------------
__device__ __forceinline__ void cp16(float* dst_sh, const float* src_g) {
    uint32_t d = (uint32_t)__cvta_generic_to_shared(dst_sh);
    asm volatile("cp.async.ca.shared.global [%0], [%1], 16;" :: "r"(d), "l"(src_g));
}
__device__ __forceinline__ void cp_commit() {
    asm volatile("cp.async.commit_group;");
}
__device__ __forceinline__ void cp_wait_all() {
    asm volatile("cp.async.wait_all;");
}

// ---------------- scratch (device globals; no runtime allocation) ----------
__device__ float d_gi[(size_t)NS * TS * GD];
__device__ float d_h0[(size_t)NS * TS * HD];
__device__ float d_g  [NS * HD];
__device__ float d_gn [NS * HD];
__device__ float d_sim[(size_t)NS * NS];
__device__ int   d_tidx[NS * NK];
__device__ float d_tval[NS * NK];
__device__ float d_colsum[NS];
__device__ float d_colZ[NS];
__device__ float d_valid[NS];
__device__ float d_concept[NS * HD];
__device__ float d_cf [NS * HD];
__device__ float d_cfn[NS * HD];
__device__ float d_hsb[NS * HD];
__device__ float d_t1 [NS * HD];
__device__ float d_t2 [NS * HD];
__device__ float d_t3 [NS * HD];
__device__ float d_t4 [NS * HD];
__device__ bf16 d_W0hi[GD * FI];    // Wih0 split
__device__ bf16 d_W0lo[GD * FI];
__device__ bf16 d_Whi[GD * HD];     // Wih1 split
__device__ bf16 d_Wlo[GD * HD];
__device__ bf16 d_gnhi[NS * HD];
__device__ bf16 d_gnlo[NS * HD];
__device__ bf16 d_cfnhi[NS * HD];
__device__ bf16 d_cfnlo[NS * HD];
__device__ bf16 d_cf2hi[NS * HD];
__device__ bf16 d_cf2lo[NS * HD];

// ---------------- fp32 GEMM: 64x64 tile (NS x 128 x 128 head GEMMs) ---------
template<bool ACT, bool SUBPRE>
__global__ __launch_bounds__(256) void k_gemm64(
    const float* __restrict__ A, const float* __restrict__ B,
    const float* __restrict__ bias, const float* __restrict__ rs,
    const float* __restrict__ pre, float* __restrict__ C,
    int M, int N, int K)
{
    __shared__ alignas(16) float As[16][68];
    __shared__ alignas(16) float Bs[16][68];
    const int bm = blockIdx.y * 64, bn = blockIdx.x * 64;
    const int tid = threadIdx.x;
    const int a_m = tid >> 2, a_k = (tid & 3) * 4;
    const int ty = tid >> 4, tx = tid & 15;
    const int m0 = ty * 4, n0 = tx * 4;

    ull acc2[2][4];
    #pragma unroll
    for (int p = 0; p < 2; p++)
        #pragma unroll
        for (int j = 0; j < 4; j++) acc2[p][j] = 0ull;

    float4 ra, rb;
    ra = *(const float4*)(A + (size_t)(bm + a_m) * K + a_k);
    rb = *(const float4*)(B + (size_t)(bn + a_m) * K + a_k);

    for (int k0 = 0; k0 < K; k0 += 16) {
        As[a_k + 0][a_m] = ra.x; As[a_k + 1][a_m] = ra.y;
        As[a_k + 2][a_m] = ra.z; As[a_k + 3][a_m] = ra.w;
        Bs[a_k + 0][a_m] = rb.x; Bs[a_k + 1][a_m] = rb.y;
        Bs[a_k + 2][a_m] = rb.z; Bs[a_k + 3][a_m] = rb.w;
        __syncthreads();
        if (k0 + 16 < K) {
            ra = *(const float4*)(A + (size_t)(bm + a_m) * K + k0 + 16 + a_k);
            rb = *(const float4*)(B + (size_t)(bn + a_m) * K + k0 + 16 + a_k);
        }
        #pragma unroll
        for (int kk = 0; kk < 16; kk++) {
            ulonglong2 aP = *(const ulonglong2*)&As[kk][m0];
            float4 b = *(const float4*)&Bs[kk][n0];
            ull bd0 = pack2(b.x, b.x), bd1 = pack2(b.y, b.y);
            ull bd2 = pack2(b.z, b.z), bd3 = pack2(b.w, b.w);
            ffma2(acc2[0][0], aP.x, bd0); ffma2(acc2[0][1], aP.x, bd1);
            ffma2(acc2[0][2], aP.x, bd2); ffma2(acc2[0][3], aP.x, bd3);
            ffma2(acc2[1][0], aP.y, bd0); ffma2(acc2[1][1], aP.y, bd1);
            ffma2(acc2[1][2], aP.y, bd2); ffma2(acc2[1][3], aP.y, bd3);
        }
        __syncthreads();
    }

    #pragma unroll
    for (int p = 0; p < 2; p++) {
        int rowA = bm + m0 + 2 * p;
        int rowB = rowA + 1;
        float rsA = rs ? rs[rowA] : 1.f;
        float rsB = rs ? rs[rowB] : 1.f;
        float va[4], vb[4];
        #pragma unroll
        for (int j = 0; j < 4; j++) {
            float2 v = unpack2(acc2[p][j]);
            float a = v.x, b = v.y;
            if (bias) { float bj = bias[bn + n0 + j]; a += bj; b += bj; }
            if (ACT) {
                a = a > 0.f ? a : SLOPE_F * a;
                b = b > 0.f ? b : SLOPE_F * b;
            }
            a *= rsA; b *= rsB;
            if (SUBPRE) {
                a = pre[(size_t)rowA * N + bn + n0 + j] - a;
                b = pre[(size_t)rowB * N + bn + n0 + j] - b;
            }
            va[j] = a; vb[j] = b;
        }
        *(float4*)(C + (size_t)rowA * N + bn + n0) =
            make_float4(va[0], va[1], va[2], va[3]);
        *(float4*)(C + (size_t)rowB * N + bn + n0) =
            make_float4(vb[0], vb[1], vb[2], vb[3]);
    }
}

// ---------------- dual fp32 GEMM: fore + back from shared A (hs) ------------
__global__ __launch_bounds__(256) void k_gemm64_dual(
    const float* __restrict__ A,
    const float* __restrict__ Wf, const float* __restrict__ bfv,
    const float* __restrict__ Wb, const float* __restrict__ bbv,
    const float* __restrict__ pre,
    float* __restrict__ Cf, float* __restrict__ Cb,
    int M, int N, int K)
{
    __shared__ alignas(16) float As[16][68];
    __shared__ alignas(16) float BsF[16][68];
    __shared__ alignas(16) float BsB[16][68];
    const int bm = blockIdx.y * 64, bn = blockIdx.x * 64;
    const int tid = threadIdx.x;
    const int a_m = tid >> 2, a_k = (tid & 3) * 4;
    const int ty = tid >> 4, tx = tid & 15;
    const int m0 = ty * 4, n0 = tx * 4;

    ull accF[2][4], accB[2][4];
    #pragma unroll
    for (int p = 0; p < 2; p++)
        #pragma unroll
        for (int j = 0; j < 4; j++) { accF[p][j] = 0ull; accB[p][j] = 0ull; }

    float4 ra, rbf, rbb;
    ra  = *(const float4*)(A  + (size_t)(bm + a_m) * K + a_k);
    rbf = *(const float4*)(Wf + (size_t)(bn + a_m) * K + a_k);
    rbb = *(const float4*)(Wb + (size_t)(bn + a_m) * K + a_k);

    for (int k0 = 0; k0 < K; k0 += 16) {
        As[a_k + 0][a_m] = ra.x; As[a_k + 1][a_m] = ra.y;
        As[a_k + 2][a_m] = ra.z; As[a_k + 3][a_m] = ra.w;
        BsF[a_k + 0][a_m] = rbf.x; BsF[a_k + 1][a_m] = rbf.y;
        BsF[a_k + 2][a_m] = rbf.z; BsF[a_k + 3][a_m] = rbf.w;
        BsB[a_k + 0][a_m] = rbb.x; BsB[a_k + 1][a_m] = rbb.y;
        BsB[a_k + 2][a_m] = rbb.z; BsB[a_k + 3][a_m] = rbb.w;
        __syncthreads();
        if (k0 + 16 < K) {
            ra  = *(const float4*)(A  + (size_t)(bm + a_m) * K + k0 + 16 + a_k);
            rbf = *(const float4*)(Wf + (size_t)(bn + a_m) * K + k0 + 16 + a_k);
            rbb = *(const float4*)(Wb + (size_t)(bn + a_m) * K + k0 + 16 + a_k);
        }
        #pragma unroll
        for (int kk = 0; kk < 16; kk++) {
            ulonglong2 aP = *(const ulonglong2*)&As[kk][m0];
            float4 bf = *(const float4*)&BsF[kk][n0];
            float4 bb = *(const float4*)&BsB[kk][n0];
            ull f0 = pack2(bf.x, bf.x), f1 = pack2(bf.y, bf.y);
            ull f2 = pack2(bf.z, bf.z), f3 = pack2(bf.w, bf.w);
            ull g0 = pack2(bb.x, bb.x), g1 = pack2(bb.y, bb.y);
            ull g2 = pack2(bb.z, bb.z), g3 = pack2(bb.w, bb.w);
            ffma2(accF[0][0], aP.x, f0); ffma2(accF[0][1], aP.x, f1);
            ffma2(accF[0][2], aP.x, f2); ffma2(accF[0][3], aP.x, f3);
            ffma2(accF[1][0], aP.y, f0); ffma2(accF[1][1], aP.y, f1);
            ffma2(accF[1][2], aP.y, f2); ffma2(accF[1][3], aP.y, f3);
            ffma2(accB[0][0], aP.x, g0); ffma2(accB[0][1], aP.x, g1);
            ffma2(accB[0][2], aP.x, g2); ffma2(accB[0][3], aP.x, g3);
            ffma2(accB[1][0], aP.y, g0); ffma2(accB[1][1], aP.y, g1);
            ffma2(accB[1][2], aP.y, g2); ffma2(accB[1][3], aP.y, g3);
        }
        __syncthreads();
    }

    #pragma unroll
    for (int p = 0; p < 2; p++) {
        int rowA = bm + m0 + 2 * p;
        int rowB = rowA + 1;
        float vfA[4], vfB[4], vbA[4], vbB[4];
        #pragma unroll
        for (int j = 0; j < 4; j++) {
            float2 vf = unpack2(accF[p][j]);
            float2 vb = unpack2(accB[p][j]);
            float fa = vf.x + bfv[bn + n0 + j];
            float fb = vf.y + bfv[bn + n0 + j];
            float ba = vb.x + bbv[bn + n0 + j];
            float bb2 = vb.y + bbv[bn + n0 + j];
            fa = fa > 0.f ? fa : SLOPE_F * fa;
            fb = fb > 0.f ? fb : SLOPE_F * fb;
            ba = ba > 0.f ? ba : SLOPE_F * ba;
            bb2 = bb2 > 0.f ? bb2 : SLOPE_F * bb2;
            vfA[j] = fa; vfB[j] = fb;
            vbA[j] = pre[(size_t)rowA * N + bn + n0 + j] - ba;
            vbB[j] = pre[(size_t)rowB * N + bn + n0 + j] - bb2;
        }
        *(float4*)(Cf + (size_t)rowA * N + bn + n0) =
            make_float4(vfA[0], vfA[1], vfA[2], vfA[3]);
        *(float4*)(Cf + (size_t)rowB * N + bn + n0) =
            make_float4(vfB[0], vfB[1], vfB[2], vfB[3]);
        *(float4*)(Cb + (size_t)rowA * N + bn + n0) =
            make_float4(vbA[0], vbA[1], vbA[2], vbA[3]);
        *(float4*)(Cb + (size_t)rowB * N + bn + n0) =
            make_float4(vbB[0], vbB[1], vbB[2], vbB[3]);
    }
}

// reduce over split-K partial slices: C = sum_z P[z]
__global__ void k_reduce(const float* __restrict__ P, float* __restrict__ C,
                         int nslice, int total4)
{
    int i = blockIdx.x * blockDim.x + threadIdx.x;
    if (i >= total4) return;
    size_t b = (size_t)i * 4;
    float4 s = make_float4(0.f, 0.f, 0.f, 0.f);
    for (int z = 0; z < nslice; z++) {
        float4 v = *(const float4*)(P + (size_t)z * total4 * 4 + b);
        s.x += v.x; s.y += v.y; s.z += v.z; s.w += v.w;
    }
    *(float4*)(C + b) = s;
}

// ---------------- bf16 hi/lo split of TWO weight matrices (one launch) ------
__global__ void k_wsplit2(const float* __restrict__ W0,
                          bf16* __restrict__ h0, bf16* __restrict__ l0, int n0,
                          const float* __restrict__ W1,
                          bf16* __restrict__ h1, bf16* __restrict__ l1, int n1)
{
    int i = blockIdx.x * 256 + threadIdx.x;
    if (i < n0) {
        float v = W0[i];
        bf16 h = __float2bfloat16(v);
        h0[i] = h;
        l0[i] = __float2bfloat16(v - __bfloat162float(h));
    } else if (i < n0 + n1) {
        int j = i - n0;
        float v = W1[j];
        bf16 h = __float2bfloat16(v);
        h1[j] = h;
        l1[j] = __float2bfloat16(v - __bfloat162float(h));
    }
}

// ---------------- generic wmma bf16x3:  C = A @ B^T (runtime K) --------------
template<bool EXPCS>
__global__ __launch_bounds__(256) void k_wmma_nt(
    const float* __restrict__ A,
    const bf16* __restrict__ Bhi, const bf16* __restrict__ Blo,
    float* __restrict__ colZacc, float* __restrict__ C, int N, int K)
{
    __shared__ alignas(32) bf16 Ahi[128][24];
    __shared__ alignas(32) bf16 Alo[128][24];
    __shared__ alignas(32) bf16 Bh[64][24];
    __shared__ alignas(32) bf16 Bl[64][24];
    __shared__ float colsh[64];
    __shared__ float stag[8][16][16];
    const int bm = blockIdx.y * 128, bn = blockIdx.x * 64;
    const int tid = threadIdx.x, wid = tid >> 5;
    const int lane = tid & 31;
    const int wm = (wid >> 1) * 32, wn = (wid & 1) * 32;

    if (EXPCS && tid < 64) colsh[tid] = 0.f;

    wmma::fragment<wmma::accumulator, 16, 16, 16, float> acc[2][2];
    #pragma unroll
    for (int i = 0; i < 2; i++)
        #pragma unroll
        for (int j = 0; j < 2; j++) wmma::fill_fragment(acc[i][j], 0.f);

    const int a_m = tid >> 1, a_k = (tid & 1) * 8;
    const int b_n = tid >> 2, b_k = (tid & 3) * 4;

    float4 v0, v1;
    uint2 rbh, rbl;
    {
        const float* Ap = A + (size_t)(bm + a_m) * K + a_k;
        v0 = *(const float4*)Ap;
        v1 = *(const float4*)(Ap + 4);
        rbh = *(const uint2*)(Bhi + (size_t)(bn + b_n) * K + b_k);
        rbl = *(const uint2*)(Blo + (size_t)(bn + b_n) * K + b_k);
    }

    for (int k0 = 0; k0 < K; k0 += 16) {
        float av[8] = {v0.x, v0.y, v0.z, v0.w, v1.x, v1.y, v1.z, v1.w};
        bf16 hb[8], lb[8];
        #pragma unroll
        for (int q = 0; q < 8; q++) {
            bf16 h = __float2bfloat16(av[q]);
            hb[q] = h;
            lb[q] = __float2bfloat16(av[q] - __bfloat162float(h));
        }
        *(uint4*)&Ahi[a_m][a_k] = *(uint4*)hb;
        *(uint4*)&Alo[a_m][a_k] = *(uint4*)lb;
        *(uint2*)&Bh[b_n][b_k] = rbh;
        *(uint2*)&Bl[b_n][b_k] = rbl;
        __syncthreads();
        if (k0 + 16 < K) {
            const float* Ap = A + (size_t)(bm + a_m) * K + (k0 + 16) + a_k;
            v0 = *(const float4*)Ap;
            v1 = *(const float4*)(Ap + 4);
            rbh = *(const uint2*)(Bhi + (size_t)(bn + b_n) * K + (k0 + 16) + b_k);
            rbl = *(const uint2*)(Blo + (size_t)(bn + b_n) * K + (k0 + 16) + b_k);
        }

        wmma::fragment<wmma::matrix_a, 16, 16, 16, bf16, wmma::row_major> af[2];
        wmma::fragment<wmma::matrix_b, 16, 16, 16, bf16, wmma::col_major> bfr[2];
        wmma::load_matrix_sync(af[0], &Ahi[wm][0], 24);
        wmma::load_matrix_sync(af[1], &Ahi[wm + 16][0], 24);
        wmma::load_matrix_sync(bfr[0], &Bh[wn][0], 24);
        wmma::load_matrix_sync(bfr[1], &Bh[wn + 16][0], 24);
        #pragma unroll
        for (int i = 0; i < 2; i++)
            #pragma unroll
            for (int j = 0; j < 2; j++)
                wmma::mma_sync(acc[i][j], af[i], bfr[j], acc[i][j]);
        wmma::load_matrix_sync(bfr[0], &Bl[wn][0], 24);
        wmma::load_matrix_sync(bfr[1], &Bl[wn + 16][0], 24);
        #pragma unroll
        for (int i = 0; i < 2; i++)
            #pragma unroll
            for (int j = 0; j < 2; j++)
                wmma::mma_sync(acc[i][j], af[i], bfr[j], acc[i][j]);
        wmma::load_matrix_sync(af[0], &Alo[wm][0], 24);
        wmma::load_matrix_sync(af[1], &Alo[wm + 16][0], 24);
        wmma::load_matrix_sync(bfr[0], &Bh[wn][0], 24);
        wmma::load_matrix_sync(bfr[1], &Bh[wn + 16][0], 24);
        #pragma unroll
        for (int i = 0; i < 2; i++)
            #pragma unroll
            for (int j = 0; j < 2; j++)
                wmma::mma_sync(acc[i][j], af[i], bfr[j], acc[i][j]);
        __syncthreads();
    }

    #pragma unroll
    for (int i = 0; i < 2; i++)
        #pragma unroll
        for (int j = 0; j < 2; j++) {
            if (EXPCS) {
                #pragma unroll
                for (int e = 0; e < acc[i][j].num_elements; e++)
                    acc[i][j].x[e] = __expf(acc[i][j].x[e]);
                wmma::store_matrix_sync(&stag[wid][0][0], acc[i][j], 16,
                                        wmma::mem_row_major);
                __syncwarp();
                if (lane < 16) {
                    float s = 0.f;
                    #pragma unroll
                    for (int r = 0; r < 16; r++) s += stag[wid][r][lane];
                    atomicAdd(&colsh[wn + 16 * j + lane], s);
                }
                __syncwarp();
            }
            wmma::store_matrix_sync(
                C + (size_t)(bm + wm + 16 * i) * N + bn + wn + 16 * j,
                acc[i][j], N, wmma::mem_row_major);
        }

    if (EXPCS) {
        __syncthreads();
        if (tid < 64) atomicAdd(&colZacc[bn + tid], colsh[tid]);
    }
}

// ---------------- wmma bf16x3:  P[z] = A[:, kslice] @ B[kslice, :] -----------
__global__ __launch_bounds__(256) void k_wmma_nn(
    const float* __restrict__ A,
    const bf16* __restrict__ Bhi, const bf16* __restrict__ Blo,
    float* __restrict__ P, int M, int K, int ksplit)
{
    __shared__ alignas(32) bf16 Ahi[128][24];
    __shared__ alignas(32) bf16 Alo[128][24];
    __shared__ alignas(32) bf16 Bh[16][72];
    __shared__ alignas(32) bf16 Bl[16][72];
    const int bm = blockIdx.y * 128, bn = blockIdx.x * 64;
    const int tid = threadIdx.x, wid = tid >> 5;
    const int wm = (wid >> 1) * 32, wn = (wid & 1) * 32;
    const int kbase = blockIdx.z * ksplit;
    const int kend = kbase + ksplit;

    wmma::fragment<wmma::accumulator, 16, 16, 16, float> acc[2][2];
    #pragma unroll
    for (int i = 0; i < 2; i++)
        #pragma unroll
        for (int j = 0; j < 2; j++) wmma::fill_fragment(acc[i][j], 0.f);

    const int a_m = tid >> 1, a_k = (tid & 1) * 8;
    const int bk_r = tid >> 4, bn_c = (tid & 15) * 4;

    float4 v0, v1;
    uint2 rbh, rbl;
    {
        const float* Ap = A + (size_t)(bm + a_m) * K + kbase + a_k;
        v0 = *(const float4*)Ap;
        v1 = *(const float4*)(Ap + 4);
        rbh = *(const uint2*)(Bhi + (size_t)(kbase + bk_r) * HD + bn + bn_c);
        rbl = *(const uint2*)(Blo + (size_t)(kbase + bk_r) * HD + bn + bn_c);
    }

    for (int k0 = kbase; k0 < kend; k0 += 16) {
        float av[8] = {v0.x, v0.y, v0.z, v0.w, v1.x, v1.y, v1.z, v1.w};
        bf16 hb[8], lb[8];
        #pragma unroll
        for (int q = 0; q < 8; q++) {
            bf16 h = __float2bfloat16(av[q]);
            hb[q] = h;
            lb[q] = __float2bfloat16(av[q] - __bfloat162float(h));
        }
        *(uint4*)&Ahi[a_m][a_k] = *(uint4*)hb;
        *(uint4*)&Alo[a_m][a_k] = *(uint4*)lb;
        *(uint2*)&Bh[bk_r][bn_c] = rbh;
        *(uint2*)&Bl[bk_r][bn_c] = rbl;
        __syncthreads();
        if (k0 + 16 < kend) {
            const float* Ap = A + (size_t)(bm + a_m) * K + (k0 + 16) + a_k;
            v0 = *(const float4*)Ap;
            v1 = *(const float4*)(Ap + 4);
            rbh = *(const uint2*)(Bhi + (size_t)(k0 + 16 + bk_r) * HD + bn + bn_c);
            rbl = *(const uint2*)(Blo + (size_t)(k0 + 16 + bk_r) * HD + bn + bn_c);
        }

        wmma::fragment<wmma::matrix_a, 16, 16, 16, bf16, wmma::row_major> af[2];
        wmma::fragment<wmma::matrix_b, 16, 16, 16, bf16, wmma::row_major> bfr[2];
        wmma::load_matrix_sync(af[0], &Ahi[wm][0], 24);
        wmma::load_matrix_sync(af[1], &Ahi[wm + 16][0], 24);
        wmma::load_matrix_sync(bfr[0], &Bh[0][wn], 72);
        wmma::load_matrix_sync(bfr[1], &Bh[0][wn + 16], 72);
        #pragma unroll
        for (int i = 0; i < 2; i++)
            #pragma unroll
            for (int j = 0; j < 2; j++)
                wmma::mma_sync(acc[i][j], af[i], bfr[j], acc[i][j]);
        wmma::load_matrix_sync(bfr[0], &Bl[0][wn], 72);
        wmma::load_matrix_sync(bfr[1], &Bl[0][wn + 16], 72);
        #pragma unroll
        for (int i = 0; i < 2; i++)
            #pragma unroll
            for (int j = 0; j < 2; j++)
                wmma::mma_sync(acc[i][j], af[i], bfr[j], acc[i][j]);
        wmma::load_matrix_sync(af[0], &Alo[wm][0], 24);
        wmma::load_matrix_sync(af[1], &Alo[wm + 16][0], 24);
        wmma::load_matrix_sync(bfr[0], &Bh[0][wn], 72);
        wmma::load_matrix_sync(bfr[1], &Bh[0][wn + 16], 72);
        #pragma unroll
        for (int i = 0; i < 2; i++)
            #pragma unroll
            for (int j = 0; j < 2; j++)
                wmma::mma_sync(acc[i][j], af[i], bfr[j], acc[i][j]);
        __syncthreads();
    }

    float* Pw = P + (size_t)blockIdx.z * ((size_t)M * HD);
    #pragma unroll
    for (int i = 0; i < 2; i++)
        #pragma unroll
        for (int j = 0; j < 2; j++)
            wmma::store_matrix_sync(
                Pw + (size_t)(bm + wm + 16 * i) * HD + bn + wn + 16 * j,
                acc[i][j], HD, wmma::mem_row_major);
}

// ---------------- persistent GRU recurrent kernel (R14 geometry) ------------
// 384 threads, mapping (2 outputs, half-k): o = tid%192, half = tid/192.
// Thread owns Whh rows o and o+192 restricted to its 64-element k-half.
// Matvec: two rows/iter, 4 chains. gi staged via cp.async double buffer.
// t=0 fast path: h==0 so gh is exactly the bias (skip the matvec).
template<bool WRITE_SEQ>
__global__ __launch_bounds__(384, 1) void k_gru(
    const float* __restrict__ gi, const float* __restrict__ Whh,
    const float* __restrict__ bhh, const float* __restrict__ bih,
    float* __restrict__ hout)
{
    extern __shared__ float sm[];
    float* h_sh = sm;
    float* ghA  = sm + GRROWS * HD;
    float* ghB  = ghA + GRROWS * GD;
    float* gi_sh = ghB + GRROWS * GD;
    __shared__ float bih_sh[GD];
    const int tid = threadIdx.x;
    const int o = tid % 192;
    const int half = tid / 192;
    const int o2 = o + 192;
    const int base = blockIdx.x * GRROWS;
    const int rows = (NS - base < GRROWS) ? (NS - base) : GRROWS;
    float* ghOut = half ? ghB : ghA;

    ull wq[64];
    {
        const ulonglong2* wg0 =
            (const ulonglong2*)(Whh + (size_t)o * HD + half * 64);
        const ulonglong2* wg1 =
            (const ulonglong2*)(Whh + (size_t)o2 * HD + half * 64);
        #pragma unroll
        for (int q = 0; q < 16; q++) {
            ulonglong2 t0 = wg0[q];
            wq[2 * q] = t0.x; wq[2 * q + 1] = t0.y;
        }
        #pragma unroll
        for (int q = 0; q < 16; q++) {
            ulonglong2 t1 = wg1[q];
            wq[32 + 2 * q] = t1.x; wq[32 + 2 * q + 1] = t1.y;
        }
    }
    const float bo0 = half ? 0.f : bhh[o];
    const float bo1 = half ? 0.f : bhh[o2];
    bih_sh[tid] = bih[tid];
    for (int idx = tid; idx < rows * HD; idx += 384) h_sh[idx] = 0.f;

    const int pr = tid / 12, pc = tid % 12;
    const bool pact = (pr < rows);
    {
        const float* src = gi + ((size_t)(base + pr) * TS + 0) * GD;
        if (pact) {
            #pragma unroll
            for (int i = 0; i < 8; i++) {
                int f = pc + 12 * i;
                cp16(gi_sh + pr * GD + f * 4, src + f * 4);
            }
        }
        cp_commit();
    }
    __syncthreads();

    for (int t = 0; t < TS; t++) {
        if (t == 0) {
            // h == 0 -> gh is just the bias
            #pragma unroll 2
            for (int r = 0; r < rows; r++) {
                ghOut[r * GD + o]  = bo0;
                ghOut[r * GD + o2] = bo1;
            }
        } else {
            #pragma unroll 1
            for (int r = 0; r < rows; r += 2) {
                const ulonglong2* hp0 =
                    (const ulonglong2*)(h_sh + r * HD + half * 64);
                const ulonglong2* hp1 =
                    (const ulonglong2*)(h_sh + (r + 1) * HD + half * 64);
                ull a0 = 0ull, b0 = 0ull, a1 = 0ull, b1 = 0ull;
                #pragma unroll
                for (int q = 0; q < 16; q++) {
                    ulonglong2 x0 = hp0[q];
                    ulonglong2 x1 = hp1[q];
                    ffma2(a0, x0.x, wq[2 * q]);
                    ffma2(b0, x0.x, wq[32 + 2 * q]);
                    ffma2(a1, x1.x, wq[2 * q]);
                    ffma2(b1, x1.x, wq[32 + 2 * q]);
                    ffma2(a0, x0.y, wq[2 * q + 1]);
                    ffma2(b0, x0.y, wq[32 + 2 * q + 1]);
                    ffma2(a1, x1.y, wq[2 * q + 1]);
                    ffma2(b1, x1.y, wq[32 + 2 * q + 1]);
                }
                float2 pa0 = unpack2(a0), pb0 = unpack2(b0);
                float2 pa1 = unpack2(a1), pb1 = unpack2(b1);
                ghOut[r * GD + o]        = (pa0.x + pa0.y) + bo0;
                ghOut[r * GD + o2]       = (pb0.x + pb0.y) + bo1;
                ghOut[(r + 1) * GD + o]  = (pa1.x + pa1.y) + bo0;
                ghOut[(r + 1) * GD + o2] = (pb1.x + pb1.y) + bo1;
            }
        }
        cp_wait_all();
        __syncthreads();
        #pragma unroll 1
        for (int idx = tid; idx < rows * HD; idx += 384) {
            int r = idx >> 7, j = idx & 127;
            float gir = gi_sh[r * GD + j]       + bih_sh[j];
            float giz = gi_sh[r * GD + j + 128] + bih_sh[j + 128];
            float gin = gi_sh[r * GD + j + 256] + bih_sh[j + 256];
            float ghr = ghA[r * GD + j]       + ghB[r * GD + j];
            float ghz = ghA[r * GD + j + 128] + ghB[r * GD + j + 128];
            float ghn = ghA[r * GD + j + 256] + ghB[r * GD + j + 256];
            float rg = __fdividef(1.f, 1.f + __expf(-(gir + ghr)));
            float zg = __fdividef(1.f, 1.f + __expf(-(giz + ghz)));
            float a2 = gin + rg * ghn;
            float ng = 1.f - __fdividef(2.f, __expf(2.f * a2) + 1.f);
            float hprev = h_sh[idx];
            float hn = (1.f - zg) * ng + zg * hprev;
            h_sh[idx] = hn;
            if (WRITE_SEQ)
                hout[((size_t)(base + r) * TS + t) * HD + j] = hn;
            else if (t == TS - 1)
                hout[(size_t)(base + r) * HD + j] = hn;
        }
        __syncthreads();
        if (t + 1 < TS) {
            const float* src = gi + ((size_t)(base + pr) * TS + (t + 1)) * GD;
            if (pact) {
                #pragma unroll
                for (int i = 0; i < 8; i++) {
                    int f = pc + 12 * i;
                    cp16(gi_sh + pr * GD + f * 4, src + f * 4);
                }
            }
            cp_commit();
        }
    }
}

// ---------------- small helpers --------------------------------------------
__global__ void k_zero(float* p, int n) {
    int i = blockIdx.x * blockDim.x + threadIdx.x;
    if (i < n) p[i] = 0.f;
}

// row L2-normalize; also emit bf16 hi/lo split of the normalized row
__global__ void k_rownorm(const float* __restrict__ src, float* __restrict__ dst,
                          bf16* __restrict__ hi, bf16* __restrict__ lo)
{
    int row = blockIdx.x * 8 + (threadIdx.x >> 5);
    int lane = threadIdx.x & 31;
    const float4* s4 = (const float4*)(src + (size_t)row * HD);
    float4 v = s4[lane];
    float ss = v.x*v.x + v.y*v.y + v.z*v.z + v.w*v.w;
    #pragma unroll
    for (int off = 16; off; off >>= 1) ss += __shfl_xor_sync(0xffffffffu, ss, off);
    float n = sqrtf(ss);
    float inv = (n > 0.f) ? 1.f / n : 0.f;
    float4 r = make_float4(v.x*inv, v.y*inv, v.z*inv, v.w*inv);
    ((float4*)(dst + (size_t)row * HD))[lane] = r;
    float rv[4] = {r.x, r.y, r.z, r.w};
    bf16 hb[4], lb[4];
    #pragma unroll
    for (int q = 0; q < 4; q++) {
        bf16 h = __float2bfloat16(rv[q]);
        hb[q] = h;
        lb[q] = __float2bfloat16(rv[q] - __bfloat162float(h));
    }
    *(uint2*)(hi + (size_t)row * HD + lane * 4) = *(uint2*)hb;
    *(uint2*)(lo + (size_t)row * HD + lane * 4) = *(uint2*)lb;
}

// cf2 = cf / colZ (row-wise), emitted as bf16 hi/lo
__global__ void k_cfscale(const float* __restrict__ cf,
                          const float* __restrict__ colZ,
                          bf16* __restrict__ hi, bf16* __restrict__ lo)
{
    int row = blockIdx.x * 8 + (threadIdx.x >> 5);
    int lane = threadIdx.x & 31;
    float rz = __fdividef(1.f, colZ[row]);
    float4 v = ((const float4*)(cf + (size_t)row * HD))[lane];
    float rv[4] = {v.x * rz, v.y * rz, v.z * rz, v.w * rz};
    bf16 hb[4], lb[4];
    #pragma unroll
    for (int q = 0; q < 4; q++) {
        bf16 h = __float2bfloat16(rv[q]);
        hb[q] = h;
        lb[q] = __float2bfloat16(rv[q] - __bfloat162float(h));
    }
    *(uint2*)(hi + (size_t)row * HD + lane * 4) = *(uint2*)hb;
    *(uint2*)(lo + (size_t)row * HD + lane * 4) = *(uint2*)lb;
}

// top-K=20 per row of |sim| (diag excluded), jax-stable ties (lowest index).
__global__ __launch_bounds__(256) void k_topk(
    const float* __restrict__ sim, int* __restrict__ tidx,
    float* __restrict__ tval, float* __restrict__ colsum)
{
    int i = blockIdx.x;
    __shared__ float sabs[NS];
    __shared__ float segv[128];
    __shared__ int   segi[128];
    __shared__ float bcv[4];
    __shared__ int   bci[4];
    const int tid = threadIdx.x;
    const float* row = sim + (size_t)i * NS;

    for (int c4 = tid; c4 < NS / 4; c4 += 256) {
        float4 v = *(const float4*)(row + c4 * 4);
        float4 a = make_float4(fabsf(v.x), fabsf(v.y), fabsf(v.z), fabsf(v.w));
        *(float4*)&sabs[c4 * 4] = a;
    }
    __syncthreads();
    if (tid == 0) sabs[i] = -1.f;
    __syncthreads();

    if (tid < 128) {
        float bv = -2.f; int bi = tid * 32;
        #pragma unroll 4
        for (int j = 0; j < 32; j++) {
            float v = sabs[tid * 32 + j];
            if (v > bv) { bv = v; bi = tid * 32 + j; }
        }
        segv[tid] = bv; segi[tid] = bi;
    }
    __syncthreads();

    for (int k = 0; k < NK; k++) {
        if (tid < 128) {
            float bv = segv[tid]; int bi = segi[tid];
            #pragma unroll
            for (int off = 16; off; off >>= 1) {
                float ov = __shfl_down_sync(0xffffffffu, bv, off);
                int   oi = __shfl_down_sync(0xffffffffu, bi, off);
                if (ov > bv || (ov == bv && oi < bi)) { bv = ov; bi = oi; }
            }
            if ((tid & 31) == 0) { bcv[tid >> 5] = bv; bci[tid >> 5] = bi; }
        }
        __syncthreads();
        if (tid < 32) {
            int bi = 0;
            if (tid == 0) {
                float bv = bcv[0]; bi = bci[0];
                #pragma unroll
                for (int w = 1; w < 4; w++)
                    if (bcv[w] > bv || (bcv[w] == bv && bci[w] < bi)) {
                        bv = bcv[w]; bi = bci[w];
                    }
                tidx[i * NK + k] = bi;
                float sv = row[bi];
                tval[i * NK + k] = sv;
                atomicAdd(&colsum[bi], sv);
                sabs[bi] = -2.f;
            }
            bi = __shfl_sync(0xffffffffu, bi, 0);
            __syncwarp();
            int s = bi >> 5;
            int idx = s * 32 + tid;
            float bv2 = sabs[idx]; int bi2 = idx;
            #pragma unroll
            for (int off = 16; off; off >>= 1) {
                float ov = __shfl_down_sync(0xffffffffu, bv2, off);
                int   oi = __shfl_down_sync(0xffffffffu, bi2, off);
                if (ov > bv2 || (ov == bv2 && oi < bi2)) { bv2 = ov; bi2 = oi; }
            }
            if (tid == 0) { segv[s] = bv2; segi[s] = bi2; }
        }
        __syncthreads();
    }
}

__global__ void k_scatter(const int* __restrict__ tidx, const float* __restrict__ tval,
                          const float* __restrict__ g, float* __restrict__ concept)
{
    int i = blockIdx.x, d = threadIdx.x;
    float gv = g[(size_t)i * HD + d];
    #pragma unroll
    for (int k = 0; k < NK; k++) {
        int c = __ldg(&tidx[i * NK + k]);
        float v = __ldg(&tval[i * NK + k]);
        atomicAdd(&concept[(size_t)c * HD + d], v * gv);
    }
}

__global__ void k_diag_valid(const float* __restrict__ colsum, const float* __restrict__ sim,
                             const float* __restrict__ g, float* __restrict__ concept,
                             float* __restrict__ valid)
{
    int j = blockIdx.x, t = threadIdx.x;
    float cs = colsum[j];
    float v = concept[(size_t)j * HD + t];
    if (cs != 0.f) {
        float dg = sim[(size_t)j * NS + j];
        v += dg * g[(size_t)j * HD + t];
        concept[(size_t)j * HD + t] = v;
    }
    float s = v;
    #pragma unroll
    for (int off = 16; off; off >>= 1) s += __shfl_xor_sync(0xffffffffu, s, off);
    __shared__ float ws[4];
    if ((t & 31) == 0) ws[t >> 5] = s;
    __syncthreads();
    if (t == 0) {
        float tot = ws[0] + ws[1] + ws[2] + ws[3];
        valid[j] = (tot != 0.f) ? 1.f : 0.f;
    }
}

__global__ void k_final(const float* __restrict__ fore, const float* __restrict__ indi,
                        const float* __restrict__ Wout, const float* __restrict__ bout,
                        float* __restrict__ out)
{
    int row = blockIdx.x * 8 + (threadIdx.x >> 5);
    int lane = threadIdx.x & 31;
    float4 a = ((const float4*)(fore + (size_t)row * HD))[lane];
    float4 b = ((const float4*)(indi + (size_t)row * HD))[lane];
    float4 w = ((const float4*)Wout)[lane];
    float s = (a.x+b.x)*w.x + (a.y+b.y)*w.y + (a.z+b.z)*w.z + (a.w+b.w)*w.w;
    #pragma unroll
    for (int off = 16; off; off >>= 1) s += __shfl_xor_sync(0xffffffffu, s, off);
    if (lane == 0) out[row] = s + bout[0];
}

// ---------------- driver -----------------------------------------------------
extern "C" void kernel_launch(void* const* d_in, const int* in_sizes, int n_in,
                              void* d_out, int out_size)
{
    const float* x     = (const float*)d_in[0];
    const float* Wih0  = (const float*)d_in[1];
    const float* Whh0  = (const float*)d_in[2];
    const float* bih0  = (const float*)d_in[3];
    const float* bhh0  = (const float*)d_in[4];
    const float* Wih1  = (const float*)d_in[5];
    const float* Whh1  = (const float*)d_in[6];
    const float* bih1  = (const float*)d_in[7];
    const float* bhh1  = (const float*)d_in[8];
    const float* W_hc  = (const float*)d_in[9];
    const float* b_hc  = (const float*)d_in[10];
    const float* W_hs  = (const float*)d_in[11];
    const float* b_hs  = (const float*)d_in[12];
    const float* W_fore= (const float*)d_in[13];
    const float* b_fore= (const float*)d_in[14];
    const float* W_back= (const float*)d_in[15];
    const float* b_back= (const float*)d_in[16];
    const float* W_indi= (const float*)d_in[17];
    const float* b_indi= (const float*)d_in[18];
    const float* W_out = (const float*)d_in[19];
    const float* b_out = (const float*)d_in[20];
    float* out = (float*)d_out;

    float *gi, *h0, *g, *gn, *sim, *colsum, *colZ, *valid, *concept;
    float *cf, *cfn, *hs, *t1, *t2, *t3, *t4, *tval;
    int* tidx;
    bf16 *w0hi, *w0lo, *whi, *wlo, *gnhi, *gnlo, *cfnhi, *cfnlo, *cf2hi, *cf2lo;
    cudaGetSymbolAddress((void**)&gi,      d_gi);
    cudaGetSymbolAddress((void**)&h0,      d_h0);
    cudaGetSymbolAddress((void**)&g,       d_g);
    cudaGetSymbolAddress((void**)&gn,      d_gn);
    cudaGetSymbolAddress((void**)&sim,     d_sim);
    cudaGetSymbolAddress((void**)&tidx,    d_tidx);
    cudaGetSymbolAddress((void**)&tval,    d_tval);
    cudaGetSymbolAddress((void**)&colsum,  d_colsum);
    cudaGetSymbolAddress((void**)&colZ,    d_colZ);
    cudaGetSymbolAddress((void**)&valid,   d_valid);
    cudaGetSymbolAddress((void**)&concept, d_concept);
    cudaGetSymbolAddress((void**)&cf,      d_cf);
    cudaGetSymbolAddress((void**)&cfn,     d_cfn);
    cudaGetSymbolAddress((void**)&hs,      d_hsb);
    cudaGetSymbolAddress((void**)&t1,      d_t1);
    cudaGetSymbolAddress((void**)&t2,      d_t2);
    cudaGetSymbolAddress((void**)&t3,      d_t3);
    cudaGetSymbolAddress((void**)&t4,      d_t4);
    cudaGetSymbolAddress((void**)&w0hi,    d_W0hi);
    cudaGetSymbolAddress((void**)&w0lo,    d_W0lo);
    cudaGetSymbolAddress((void**)&whi,     d_Whi);
    cudaGetSymbolAddress((void**)&wlo,     d_Wlo);
    cudaGetSymbolAddress((void**)&gnhi,    d_gnhi);
    cudaGetSymbolAddress((void**)&gnlo,    d_gnlo);
    cudaGetSymbolAddress((void**)&cfnhi,   d_cfnhi);
    cudaGetSymbolAddress((void**)&cfnlo,   d_cfnlo);
    cudaGetSymbolAddress((void**)&cf2hi,   d_cf2hi);
    cudaGetSymbolAddress((void**)&cf2lo,   d_cf2lo);

    // h 28*128 + ghA/ghB 2*28*384 + gi 28*384 floats = 143360 B
    const int GRU_SMEM = (GRROWS * HD + 3 * GRROWS * GD) * 4;
    cudaFuncSetAttribute((const void*)k_gru<true>,
                         cudaFuncAttributeMaxDynamicSharedMemorySize, GRU_SMEM);
    cudaFuncSetAttribute((const void*)k_gru<false>,
                         cudaFuncAttributeMaxDynamicSharedMemorySize, GRU_SMEM);

    const int MT = NS * TS;         // 262144
    const int GRU_GRID = (NS + GRROWS - 1) / GRROWS;  // 147

    // Launch order: gru0 is our 4th launch so ncu (-s 5 -c 1, one harness
    // pre-launch) captures the GRU kernel.
    // #1 split both input-weight matrices (one launch)
    k_wsplit2<<<(GD * FI + GD * HD + 255) / 256, 256>>>(
        Wih0, w0hi, w0lo, GD * FI, Wih1, whi, wlo, GD * HD);
    // #2 gi0 = x @ Wih0^T via wmma bf16x3 (K=32)
    k_wmma_nt<false><<<dim3(GD / 64, MT / 128), 256>>>(
        x, w0hi, w0lo, nullptr, gi, GD, FI);
    // #3 zero colsum
    k_zero<<<(NS + 255) / 256, 256>>>(colsum, NS);
    // #4 GRU layer 0 (writes full sequence)  <- ncu capture target
    k_gru<true><<<GRU_GRID, 384, GRU_SMEM>>>(gi, Whh0, bhh0, bih0, h0);
    // gi1 = h0 @ Wih1^T via wmma bf16x3 (K=128)
    k_wmma_nt<false><<<dim3(GD / 64, MT / 128), 256>>>(
        h0, whi, wlo, nullptr, gi, GD, HD);
    // GRU layer 1 (writes final hidden only -> g)
    k_gru<false><<<GRU_GRID, 384, GRU_SMEM>>>(gi, Whh1, bhh1, bih1, g);

    // zeros for later accumulators
    k_zero<<<(NS * HD + 255) / 256, 256>>>(concept, NS * HD);
    k_zero<<<(NS + 255) / 256, 256>>>(colZ, NS);

    // normalized g (fp32 + bf16 hi/lo); sim = gn @ gn^T via wmma bf16x3
    k_rownorm<<<NS / 8, 256>>>(g, gn, gnhi, gnlo);
    k_wmma_nt<false><<<dim3(NS / 64, NS / 128), 256>>>(
        gn, gnhi, gnlo, nullptr, sim, NS, HD);

    // top-K selection + concept aggregation
    k_topk<<<NS, 256>>>(sim, tidx, tval, colsum);
    k_scatter<<<NS, 128>>>(tidx, tval, g, concept);
    k_diag_valid<<<NS, 128>>>(colsum, sim, g, concept, valid);

    // cf = lrelu(concept @ W_hc^T + b_hc) * valid
    k_gemm64<true, false><<<dim3(HD / 64, NS / 64), 256>>>(
        concept, W_hc, b_hc, valid, nullptr, cf, NS, HD, HD);
    k_rownorm<<<NS / 8, 256>>>(cf, cfn, cfnhi, cfnlo);

    // E = exp(gn @ cfn^T) with fused column sums (wmma bf16x3)
    k_wmma_nt<true><<<dim3(NS / 64, NS / 128), 256>>>(
        gn, cfnhi, cfnlo, colZ, sim, NS, HD);

    // cf2 = cf / colZ (bf16 hi/lo); t1 = E @ cf2 (wmma, split-K=8) + reduce
    k_cfscale<<<NS / 8, 256>>>(cf, colZ, cf2hi, cf2lo);
    k_wmma_nn<<<dim3(HD / 64, NS / 128, 8), 256>>>(
        sim, cf2hi, cf2lo, gi, NS, NS, NS / 8);
    k_reduce<<<(NS * HD / 4 + 255) / 256, 256>>>(gi, t1, 8, NS * HD / 4);

    // hs = lrelu(t1 @ W_hs^T + b_hs)
    k_gemm64<true, false><<<dim3(HD / 64, NS / 64), 256>>>(
        t1, W_hs, b_hs, nullptr, nullptr, hs, NS, HD, HD);

    // fused: t2 = lrelu(hs@W_fore^T+b_fore); t3 = g - lrelu(hs@W_back^T+b_back)
    k_gemm64_dual<<<dim3(HD / 64, NS / 64), 256>>>(
        hs, W_fore, b_fore, W_back, b_back, g, t2, t3, NS, HD, HD);
    // t4 = lrelu(t3 @ W_indi^T + b_indi)
    k_gemm64<true, false><<<dim3(HD / 64, NS / 64), 256>>>(
        t3, W_indi, b_indi, nullptr, nullptr, t4, NS, HD, HD);
    k_final<<<NS / 8, 256>>>(t2, t4, W_out, b_out, out);
}

// round 17
// speedup vs baseline: 1.2353x; 1.0039x over previous
#include <cuda_runtime.h>
#include <cuda_bf16.h>
#include <mma.h>
#include <math.h>
#include <stdint.h>
#include <stddef.h>

using namespace nvcuda;

// Problem dims (fixed by the dataset)
#define NS   4096      // batch
#define TS   64        // timesteps
#define FI   32        // input features
#define HD   128       // hidden
#define GD   384       // 3*H
#define NK   20        // top-k
#define SLOPE_F 0.2f
#define GRROWS 28      // batch rows per GRU CTA (147 CTAs -> all 148 SMs)

typedef unsigned long long ull;
typedef __nv_bfloat16 bf16;

// ---------------- f32x2 packed helpers (Blackwell FFMA2) --------------------
__device__ __forceinline__ ull pack2(float lo, float hi) {
    ull r;
    asm("mov.b64 %0, {%1, %2};" : "=l"(r) : "f"(lo), "f"(hi));
    return r;
}
__device__ __forceinline__ float2 unpack2(ull v) {
    float2 r;
    asm("mov.b64 {%0, %1}, %2;" : "=f"(r.x), "=f"(r.y) : "l"(v));
    return r;
}
__device__ __forceinline__ void ffma2(ull& d, ull a, ull b) {
    asm("fma.rn.f32x2 %0, %1, %2, %0;" : "+l"(d) : "l"(a), "l"(b));
}

// ---------------- cp.async helpers -----------------------------------------
__device__ __forceinline__ void cp16(float* dst_sh, const float* src_g) {
    uint32_t d = (uint32_t)__cvta_generic_to_shared(dst_sh);
    asm volatile("cp.async.ca.shared.global [%0], [%1], 16;" :: "r"(d), "l"(src_g));
}
__device__ __forceinline__ void cp_commit() {
    asm volatile("cp.async.commit_group;");
}
__device__ __forceinline__ void cp_wait_all() {
    asm volatile("cp.async.wait_all;");
}

// ---------------- scratch (device globals; no runtime allocation) ----------
__device__ float d_gi[(size_t)NS * TS * GD];
__device__ float d_h0[(size_t)NS * TS * HD];
__device__ float d_g  [NS * HD];
__device__ float d_gn [NS * HD];
__device__ float d_sim[(size_t)NS * NS];
__device__ int   d_tidx[NS * NK];
__device__ float d_tval[NS * NK];
__device__ float d_colsum[NS];
__device__ float d_colZ[NS];
__device__ float d_valid[NS];
__device__ float d_concept[NS * HD];
__device__ float d_cf [NS * HD];
__device__ float d_cfn[NS * HD];
__device__ float d_hsb[NS * HD];
__device__ float d_t1 [NS * HD];
__device__ float d_t2 [NS * HD];
__device__ float d_t3 [NS * HD];
__device__ float d_t4 [NS * HD];
__device__ bf16 d_W0hi[GD * FI];    // Wih0 split
__device__ bf16 d_W0lo[GD * FI];
__device__ bf16 d_Whi[GD * HD];     // Wih1 split
__device__ bf16 d_Wlo[GD * HD];
__device__ bf16 d_gnhi[NS * HD];
__device__ bf16 d_gnlo[NS * HD];
__device__ bf16 d_cfnhi[NS * HD];
__device__ bf16 d_cfnlo[NS * HD];
__device__ bf16 d_cf2hi[NS * HD];
__device__ bf16 d_cf2lo[NS * HD];

// ---------------- fp32 GEMM: 64x64 tile (NS x 128 x 128 head GEMMs) ---------
template<bool ACT, bool SUBPRE>
__global__ __launch_bounds__(256) void k_gemm64(
    const float* __restrict__ A, const float* __restrict__ B,
    const float* __restrict__ bias, const float* __restrict__ rs,
    const float* __restrict__ pre, float* __restrict__ C,
    int M, int N, int K)
{
    __shared__ alignas(16) float As[16][68];
    __shared__ alignas(16) float Bs[16][68];
    const int bm = blockIdx.y * 64, bn = blockIdx.x * 64;
    const int tid = threadIdx.x;
    const int a_m = tid >> 2, a_k = (tid & 3) * 4;
    const int ty = tid >> 4, tx = tid & 15;
    const int m0 = ty * 4, n0 = tx * 4;

    ull acc2[2][4];
    #pragma unroll
    for (int p = 0; p < 2; p++)
        #pragma unroll
        for (int j = 0; j < 4; j++) acc2[p][j] = 0ull;

    float4 ra, rb;
    ra = *(const float4*)(A + (size_t)(bm + a_m) * K + a_k);
    rb = *(const float4*)(B + (size_t)(bn + a_m) * K + a_k);

    for (int k0 = 0; k0 < K; k0 += 16) {
        As[a_k + 0][a_m] = ra.x; As[a_k + 1][a_m] = ra.y;
        As[a_k + 2][a_m] = ra.z; As[a_k + 3][a_m] = ra.w;
        Bs[a_k + 0][a_m] = rb.x; Bs[a_k + 1][a_m] = rb.y;
        Bs[a_k + 2][a_m] = rb.z; Bs[a_k + 3][a_m] = rb.w;
        __syncthreads();
        if (k0 + 16 < K) {
            ra = *(const float4*)(A + (size_t)(bm + a_m) * K + k0 + 16 + a_k);
            rb = *(const float4*)(B + (size_t)(bn + a_m) * K + k0 + 16 + a_k);
        }
        #pragma unroll
        for (int kk = 0; kk < 16; kk++) {
            ulonglong2 aP = *(const ulonglong2*)&As[kk][m0];
            float4 b = *(const float4*)&Bs[kk][n0];
            ull bd0 = pack2(b.x, b.x), bd1 = pack2(b.y, b.y);
            ull bd2 = pack2(b.z, b.z), bd3 = pack2(b.w, b.w);
            ffma2(acc2[0][0], aP.x, bd0); ffma2(acc2[0][1], aP.x, bd1);
            ffma2(acc2[0][2], aP.x, bd2); ffma2(acc2[0][3], aP.x, bd3);
            ffma2(acc2[1][0], aP.y, bd0); ffma2(acc2[1][1], aP.y, bd1);
            ffma2(acc2[1][2], aP.y, bd2); ffma2(acc2[1][3], aP.y, bd3);
        }
        __syncthreads();
    }

    #pragma unroll
    for (int p = 0; p < 2; p++) {
        int rowA = bm + m0 + 2 * p;
        int rowB = rowA + 1;
        float rsA = rs ? rs[rowA] : 1.f;
        float rsB = rs ? rs[rowB] : 1.f;
        float va[4], vb[4];
        #pragma unroll
        for (int j = 0; j < 4; j++) {
            float2 v = unpack2(acc2[p][j]);
            float a = v.x, b = v.y;
            if (bias) { float bj = bias[bn + n0 + j]; a += bj; b += bj; }
            if (ACT) {
                a = a > 0.f ? a : SLOPE_F * a;
                b = b > 0.f ? b : SLOPE_F * b;
            }
            a *= rsA; b *= rsB;
            if (SUBPRE) {
                a = pre[(size_t)rowA * N + bn + n0 + j] - a;
                b = pre[(size_t)rowB * N + bn + n0 + j] - b;
            }
            va[j] = a; vb[j] = b;
        }
        *(float4*)(C + (size_t)rowA * N + bn + n0) =
            make_float4(va[0], va[1], va[2], va[3]);
        *(float4*)(C + (size_t)rowB * N + bn + n0) =
            make_float4(vb[0], vb[1], vb[2], vb[3]);
    }
}

// ---------------- dual fp32 GEMM: fore + back from shared A (hs) ------------
__global__ __launch_bounds__(256) void k_gemm64_dual(
    const float* __restrict__ A,
    const float* __restrict__ Wf, const float* __restrict__ bfv,
    const float* __restrict__ Wb, const float* __restrict__ bbv,
    const float* __restrict__ pre,
    float* __restrict__ Cf, float* __restrict__ Cb,
    int M, int N, int K)
{
    __shared__ alignas(16) float As[16][68];
    __shared__ alignas(16) float BsF[16][68];
    __shared__ alignas(16) float BsB[16][68];
    const int bm = blockIdx.y * 64, bn = blockIdx.x * 64;
    const int tid = threadIdx.x;
    const int a_m = tid >> 2, a_k = (tid & 3) * 4;
    const int ty = tid >> 4, tx = tid & 15;
    const int m0 = ty * 4, n0 = tx * 4;

    ull accF[2][4], accB[2][4];
    #pragma unroll
    for (int p = 0; p < 2; p++)
        #pragma unroll
        for (int j = 0; j < 4; j++) { accF[p][j] = 0ull; accB[p][j] = 0ull; }

    float4 ra, rbf, rbb;
    ra  = *(const float4*)(A  + (size_t)(bm + a_m) * K + a_k);
    rbf = *(const float4*)(Wf + (size_t)(bn + a_m) * K + a_k);
    rbb = *(const float4*)(Wb + (size_t)(bn + a_m) * K + a_k);

    for (int k0 = 0; k0 < K; k0 += 16) {
        As[a_k + 0][a_m] = ra.x; As[a_k + 1][a_m] = ra.y;
        As[a_k + 2][a_m] = ra.z; As[a_k + 3][a_m] = ra.w;
        BsF[a_k + 0][a_m] = rbf.x; BsF[a_k + 1][a_m] = rbf.y;
        BsF[a_k + 2][a_m] = rbf.z; BsF[a_k + 3][a_m] = rbf.w;
        BsB[a_k + 0][a_m] = rbb.x; BsB[a_k + 1][a_m] = rbb.y;
        BsB[a_k + 2][a_m] = rbb.z; BsB[a_k + 3][a_m] = rbb.w;
        __syncthreads();
        if (k0 + 16 < K) {
            ra  = *(const float4*)(A  + (size_t)(bm + a_m) * K + k0 + 16 + a_k);
            rbf = *(const float4*)(Wf + (size_t)(bn + a_m) * K + k0 + 16 + a_k);
            rbb = *(const float4*)(Wb + (size_t)(bn + a_m) * K + k0 + 16 + a_k);
        }
        #pragma unroll
        for (int kk = 0; kk < 16; kk++) {
            ulonglong2 aP = *(const ulonglong2*)&As[kk][m0];
            float4 bf = *(const float4*)&BsF[kk][n0];
            float4 bb = *(const float4*)&BsB[kk][n0];
            ull f0 = pack2(bf.x, bf.x), f1 = pack2(bf.y, bf.y);
            ull f2 = pack2(bf.z, bf.z), f3 = pack2(bf.w, bf.w);
            ull g0 = pack2(bb.x, bb.x), g1 = pack2(bb.y, bb.y);
            ull g2 = pack2(bb.z, bb.z), g3 = pack2(bb.w, bb.w);
            ffma2(accF[0][0], aP.x, f0); ffma2(accF[0][1], aP.x, f1);
            ffma2(accF[0][2], aP.x, f2); ffma2(accF[0][3], aP.x, f3);
            ffma2(accF[1][0], aP.y, f0); ffma2(accF[1][1], aP.y, f1);
            ffma2(accF[1][2], aP.y, f2); ffma2(accF[1][3], aP.y, f3);
            ffma2(accB[0][0], aP.x, g0); ffma2(accB[0][1], aP.x, g1);
            ffma2(accB[0][2], aP.x, g2); ffma2(accB[0][3], aP.x, g3);
            ffma2(accB[1][0], aP.y, g0); ffma2(accB[1][1], aP.y, g1);
            ffma2(accB[1][2], aP.y, g2); ffma2(accB[1][3], aP.y, g3);
        }
        __syncthreads();
    }

    #pragma unroll
    for (int p = 0; p < 2; p++) {
        int rowA = bm + m0 + 2 * p;
        int rowB = rowA + 1;
        float vfA[4], vfB[4], vbA[4], vbB[4];
        #pragma unroll
        for (int j = 0; j < 4; j++) {
            float2 vf = unpack2(accF[p][j]);
            float2 vb = unpack2(accB[p][j]);
            float fa = vf.x + bfv[bn + n0 + j];
            float fb = vf.y + bfv[bn + n0 + j];
            float ba = vb.x + bbv[bn + n0 + j];
            float bb2 = vb.y + bbv[bn + n0 + j];
            fa = fa > 0.f ? fa : SLOPE_F * fa;
            fb = fb > 0.f ? fb : SLOPE_F * fb;
            ba = ba > 0.f ? ba : SLOPE_F * ba;
            bb2 = bb2 > 0.f ? bb2 : SLOPE_F * bb2;
            vfA[j] = fa; vfB[j] = fb;
            vbA[j] = pre[(size_t)rowA * N + bn + n0 + j] - ba;
            vbB[j] = pre[(size_t)rowB * N + bn + n0 + j] - bb2;
        }
        *(float4*)(Cf + (size_t)rowA * N + bn + n0) =
            make_float4(vfA[0], vfA[1], vfA[2], vfA[3]);
        *(float4*)(Cf + (size_t)rowB * N + bn + n0) =
            make_float4(vfB[0], vfB[1], vfB[2], vfB[3]);
        *(float4*)(Cb + (size_t)rowA * N + bn + n0) =
            make_float4(vbA[0], vbA[1], vbA[2], vbA[3]);
        *(float4*)(Cb + (size_t)rowB * N + bn + n0) =
            make_float4(vbB[0], vbB[1], vbB[2], vbB[3]);
    }
}

// reduce over split-K partial slices: C = sum_z P[z]
__global__ void k_reduce(const float* __restrict__ P, float* __restrict__ C,
                         int nslice, int total4)
{
    int i = blockIdx.x * blockDim.x + threadIdx.x;
    if (i >= total4) return;
    size_t b = (size_t)i * 4;
    float4 s = make_float4(0.f, 0.f, 0.f, 0.f);
    for (int z = 0; z < nslice; z++) {
        float4 v = *(const float4*)(P + (size_t)z * total4 * 4 + b);
        s.x += v.x; s.y += v.y; s.z += v.z; s.w += v.w;
    }
    *(float4*)(C + b) = s;
}

// ---------------- bf16 hi/lo split of TWO weight matrices (one launch) ------
__global__ void k_wsplit2(const float* __restrict__ W0,
                          bf16* __restrict__ h0, bf16* __restrict__ l0, int n0,
                          const float* __restrict__ W1,
                          bf16* __restrict__ h1, bf16* __restrict__ l1, int n1)
{
    int i = blockIdx.x * 256 + threadIdx.x;
    if (i < n0) {
        float v = W0[i];
        bf16 h = __float2bfloat16(v);
        h0[i] = h;
        l0[i] = __float2bfloat16(v - __bfloat162float(h));
    } else if (i < n0 + n1) {
        int j = i - n0;
        float v = W1[j];
        bf16 h = __float2bfloat16(v);
        h1[j] = h;
        l1[j] = __float2bfloat16(v - __bfloat162float(h));
    }
}

// ---------------- generic wmma bf16x3:  C = A @ B^T (runtime K) --------------
// 128x128 CTA tile (8 warps, each 32x64). A fp32 split in-kernel (ONCE per
// 128-wide output block, vs twice at 128x64); Bhi/Blo [N,K] bf16 pre-split.
// Register double-buffered global loads.
// EXPCS: C = exp(raw); column sums accumulated into colZacc.
template<bool EXPCS>
__global__ __launch_bounds__(256) void k_wmma_nt(
    const float* __restrict__ A,
    const bf16* __restrict__ Bhi, const bf16* __restrict__ Blo,
    float* __restrict__ colZacc, float* __restrict__ C, int N, int K)
{
    __shared__ alignas(32) bf16 Ahi[128][24];
    __shared__ alignas(32) bf16 Alo[128][24];
    __shared__ alignas(32) bf16 Bh[128][24];
    __shared__ alignas(32) bf16 Bl[128][24];
    __shared__ float colsh[128];
    __shared__ float stag[8][16][16];
    const int bm = blockIdx.y * 128, bn = blockIdx.x * 128;
    const int tid = threadIdx.x, wid = tid >> 5;
    const int lane = tid & 31;
    const int wm = (wid >> 1) * 32, wn = (wid & 1) * 64;

    if (EXPCS && tid < 128) colsh[tid] = 0.f;

    wmma::fragment<wmma::accumulator, 16, 16, 16, float> acc[2][4];
    #pragma unroll
    for (int i = 0; i < 2; i++)
        #pragma unroll
        for (int j = 0; j < 4; j++) wmma::fill_fragment(acc[i][j], 0.f);

    const int a_m = tid >> 1, a_k = (tid & 1) * 8;

    float4 v0, v1;
    uint4 rbh, rbl;
    {
        const float* Ap = A + (size_t)(bm + a_m) * K + a_k;
        v0 = *(const float4*)Ap;
        v1 = *(const float4*)(Ap + 4);
        rbh = *(const uint4*)(Bhi + (size_t)(bn + a_m) * K + a_k);
        rbl = *(const uint4*)(Blo + (size_t)(bn + a_m) * K + a_k);
    }

    for (int k0 = 0; k0 < K; k0 += 16) {
        float av[8] = {v0.x, v0.y, v0.z, v0.w, v1.x, v1.y, v1.z, v1.w};
        bf16 hb[8], lb[8];
        #pragma unroll
        for (int q = 0; q < 8; q++) {
            bf16 h = __float2bfloat16(av[q]);
            hb[q] = h;
            lb[q] = __float2bfloat16(av[q] - __bfloat162float(h));
        }
        *(uint4*)&Ahi[a_m][a_k] = *(uint4*)hb;
        *(uint4*)&Alo[a_m][a_k] = *(uint4*)lb;
        *(uint4*)&Bh[a_m][a_k] = rbh;
        *(uint4*)&Bl[a_m][a_k] = rbl;
        __syncthreads();
        if (k0 + 16 < K) {
            const float* Ap = A + (size_t)(bm + a_m) * K + (k0 + 16) + a_k;
            v0 = *(const float4*)Ap;
            v1 = *(const float4*)(Ap + 4);
            rbh = *(const uint4*)(Bhi + (size_t)(bn + a_m) * K + (k0 + 16) + a_k);
            rbl = *(const uint4*)(Blo + (size_t)(bn + a_m) * K + (k0 + 16) + a_k);
        }

        wmma::fragment<wmma::matrix_a, 16, 16, 16, bf16, wmma::row_major> af[2];
        wmma::fragment<wmma::matrix_b, 16, 16, 16, bf16, wmma::col_major> bfr[4];
        // hi * hi
        wmma::load_matrix_sync(af[0], &Ahi[wm][0], 24);
        wmma::load_matrix_sync(af[1], &Ahi[wm + 16][0], 24);
        #pragma unroll
        for (int j = 0; j < 4; j++)
            wmma::load_matrix_sync(bfr[j], &Bh[wn + 16 * j][0], 24);
        #pragma unroll
        for (int i = 0; i < 2; i++)
            #pragma unroll
            for (int j = 0; j < 4; j++)
                wmma::mma_sync(acc[i][j], af[i], bfr[j], acc[i][j]);
        // hi * lo
        #pragma unroll
        for (int j = 0; j < 4; j++)
            wmma::load_matrix_sync(bfr[j], &Bl[wn + 16 * j][0], 24);
        #pragma unroll
        for (int i = 0; i < 2; i++)
            #pragma unroll
            for (int j = 0; j < 4; j++)
                wmma::mma_sync(acc[i][j], af[i], bfr[j], acc[i][j]);
        // lo * hi
        wmma::load_matrix_sync(af[0], &Alo[wm][0], 24);
        wmma::load_matrix_sync(af[1], &Alo[wm + 16][0], 24);
        #pragma unroll
        for (int j = 0; j < 4; j++)
            wmma::load_matrix_sync(bfr[j], &Bh[wn + 16 * j][0], 24);
        #pragma unroll
        for (int i = 0; i < 2; i++)
            #pragma unroll
            for (int j = 0; j < 4; j++)
                wmma::mma_sync(acc[i][j], af[i], bfr[j], acc[i][j]);
        __syncthreads();
    }

    #pragma unroll
    for (int i = 0; i < 2; i++)
        #pragma unroll
        for (int j = 0; j < 4; j++) {
            if (EXPCS) {
                #pragma unroll
                for (int e = 0; e < acc[i][j].num_elements; e++)
                    acc[i][j].x[e] = __expf(acc[i][j].x[e]);
                wmma::store_matrix_sync(&stag[wid][0][0], acc[i][j], 16,
                                        wmma::mem_row_major);
                __syncwarp();
                if (lane < 16) {
                    float s = 0.f;
                    #pragma unroll
                    for (int r = 0; r < 16; r++) s += stag[wid][r][lane];
                    atomicAdd(&colsh[wn + 16 * j + lane], s);
                }
                __syncwarp();
            }
            wmma::store_matrix_sync(
                C + (size_t)(bm + wm + 16 * i) * N + bn + wn + 16 * j,
                acc[i][j], N, wmma::mem_row_major);
        }

    if (EXPCS) {
        __syncthreads();
        if (tid < 128) atomicAdd(&colZacc[bn + tid], colsh[tid]);
    }
}

// ---------------- wmma bf16x3:  P[z] = A[:, kslice] @ B[kslice, :] -----------
__global__ __launch_bounds__(256) void k_wmma_nn(
    const float* __restrict__ A,
    const bf16* __restrict__ Bhi, const bf16* __restrict__ Blo,
    float* __restrict__ P, int M, int K, int ksplit)
{
    __shared__ alignas(32) bf16 Ahi[128][24];
    __shared__ alignas(32) bf16 Alo[128][24];
    __shared__ alignas(32) bf16 Bh[16][72];
    __shared__ alignas(32) bf16 Bl[16][72];
    const int bm = blockIdx.y * 128, bn = blockIdx.x * 64;
    const int tid = threadIdx.x, wid = tid >> 5;
    const int wm = (wid >> 1) * 32, wn = (wid & 1) * 32;
    const int kbase = blockIdx.z * ksplit;
    const int kend = kbase + ksplit;

    wmma::fragment<wmma::accumulator, 16, 16, 16, float> acc[2][2];
    #pragma unroll
    for (int i = 0; i < 2; i++)
        #pragma unroll
        for (int j = 0; j < 2; j++) wmma::fill_fragment(acc[i][j], 0.f);

    const int a_m = tid >> 1, a_k = (tid & 1) * 8;
    const int bk_r = tid >> 4, bn_c = (tid & 15) * 4;

    float4 v0, v1;
    uint2 rbh, rbl;
    {
        const float* Ap = A + (size_t)(bm + a_m) * K + kbase + a_k;
        v0 = *(const float4*)Ap;
        v1 = *(const float4*)(Ap + 4);
        rbh = *(const uint2*)(Bhi + (size_t)(kbase + bk_r) * HD + bn + bn_c);
        rbl = *(const uint2*)(Blo + (size_t)(kbase + bk_r) * HD + bn + bn_c);
    }

    for (int k0 = kbase; k0 < kend; k0 += 16) {
        float av[8] = {v0.x, v0.y, v0.z, v0.w, v1.x, v1.y, v1.z, v1.w};
        bf16 hb[8], lb[8];
        #pragma unroll
        for (int q = 0; q < 8; q++) {
            bf16 h = __float2bfloat16(av[q]);
            hb[q] = h;
            lb[q] = __float2bfloat16(av[q] - __bfloat162float(h));
        }
        *(uint4*)&Ahi[a_m][a_k] = *(uint4*)hb;
        *(uint4*)&Alo[a_m][a_k] = *(uint4*)lb;
        *(uint2*)&Bh[bk_r][bn_c] = rbh;
        *(uint2*)&Bl[bk_r][bn_c] = rbl;
        __syncthreads();
        if (k0 + 16 < kend) {
            const float* Ap = A + (size_t)(bm + a_m) * K + (k0 + 16) + a_k;
            v0 = *(const float4*)Ap;
            v1 = *(const float4*)(Ap + 4);
            rbh = *(const uint2*)(Bhi + (size_t)(k0 + 16 + bk_r) * HD + bn + bn_c);
            rbl = *(const uint2*)(Blo + (size_t)(k0 + 16 + bk_r) * HD + bn + bn_c);
        }

        wmma::fragment<wmma::matrix_a, 16, 16, 16, bf16, wmma::row_major> af[2];
        wmma::fragment<wmma::matrix_b, 16, 16, 16, bf16, wmma::row_major> bfr[2];
        wmma::load_matrix_sync(af[0], &Ahi[wm][0], 24);
        wmma::load_matrix_sync(af[1], &Ahi[wm + 16][0], 24);
        wmma::load_matrix_sync(bfr[0], &Bh[0][wn], 72);
        wmma::load_matrix_sync(bfr[1], &Bh[0][wn + 16], 72);
        #pragma unroll
        for (int i = 0; i < 2; i++)
            #pragma unroll
            for (int j = 0; j < 2; j++)
                wmma::mma_sync(acc[i][j], af[i], bfr[j], acc[i][j]);
        wmma::load_matrix_sync(bfr[0], &Bl[0][wn], 72);
        wmma::load_matrix_sync(bfr[1], &Bl[0][wn + 16], 72);
        #pragma unroll
        for (int i = 0; i < 2; i++)
            #pragma unroll
            for (int j = 0; j < 2; j++)
                wmma::mma_sync(acc[i][j], af[i], bfr[j], acc[i][j]);
        wmma::load_matrix_sync(af[0], &Alo[wm][0], 24);
        wmma::load_matrix_sync(af[1], &Alo[wm + 16][0], 24);
        wmma::load_matrix_sync(bfr[0], &Bh[0][wn], 72);
        wmma::load_matrix_sync(bfr[1], &Bh[0][wn + 16], 72);
        #pragma unroll
        for (int i = 0; i < 2; i++)
            #pragma unroll
            for (int j = 0; j < 2; j++)
                wmma::mma_sync(acc[i][j], af[i], bfr[j], acc[i][j]);
        __syncthreads();
    }

    float* Pw = P + (size_t)blockIdx.z * ((size_t)M * HD);
    #pragma unroll
    for (int i = 0; i < 2; i++)
        #pragma unroll
        for (int j = 0; j < 2; j++)
            wmma::store_matrix_sync(
                Pw + (size_t)(bm + wm + 16 * i) * HD + bn + wn + 16 * j,
                acc[i][j], HD, wmma::mem_row_major);
}

// ---------------- persistent GRU recurrent kernel (R14 geometry) ------------
// 384 threads, (2 outputs, half-k). t=0 fast path writes bias directly.
template<bool WRITE_SEQ>
__global__ __launch_bounds__(384, 1) void k_gru(
    const float* __restrict__ gi, const float* __restrict__ Whh,
    const float* __restrict__ bhh, const float* __restrict__ bih,
    float* __restrict__ hout)
{
    extern __shared__ float sm[];
    float* h_sh = sm;
    float* ghA  = sm + GRROWS * HD;
    float* ghB  = ghA + GRROWS * GD;
    float* gi_sh = ghB + GRROWS * GD;
    __shared__ float bih_sh[GD];
    const int tid = threadIdx.x;
    const int o = tid % 192;
    const int half = tid / 192;
    const int o2 = o + 192;
    const int base = blockIdx.x * GRROWS;
    const int rows = (NS - base < GRROWS) ? (NS - base) : GRROWS;
    float* ghOut = half ? ghB : ghA;

    ull wq[64];
    {
        const ulonglong2* wg0 =
            (const ulonglong2*)(Whh + (size_t)o * HD + half * 64);
        const ulonglong2* wg1 =
            (const ulonglong2*)(Whh + (size_t)o2 * HD + half * 64);
        #pragma unroll
        for (int q = 0; q < 16; q++) {
            ulonglong2 t0 = wg0[q];
            wq[2 * q] = t0.x; wq[2 * q + 1] = t0.y;
        }
        #pragma unroll
        for (int q = 0; q < 16; q++) {
            ulonglong2 t1 = wg1[q];
            wq[32 + 2 * q] = t1.x; wq[32 + 2 * q + 1] = t1.y;
        }
    }
    const float bo0 = half ? 0.f : bhh[o];
    const float bo1 = half ? 0.f : bhh[o2];
    bih_sh[tid] = bih[tid];
    for (int idx = tid; idx < rows * HD; idx += 384) h_sh[idx] = 0.f;

    const int pr = tid / 12, pc = tid % 12;
    const bool pact = (pr < rows);
    {
        const float* src = gi + ((size_t)(base + pr) * TS + 0) * GD;
        if (pact) {
            #pragma unroll
            for (int i = 0; i < 8; i++) {
                int f = pc + 12 * i;
                cp16(gi_sh + pr * GD + f * 4, src + f * 4);
            }
        }
        cp_commit();
    }
    __syncthreads();

    for (int t = 0; t < TS; t++) {
        if (t == 0) {
            #pragma unroll 2
            for (int r = 0; r < rows; r++) {
                ghOut[r * GD + o]  = bo0;
                ghOut[r * GD + o2] = bo1;
            }
        } else {
            #pragma unroll 1
            for (int r = 0; r < rows; r += 2) {
                const ulonglong2* hp0 =
                    (const ulonglong2*)(h_sh + r * HD + half * 64);
                const ulonglong2* hp1 =
                    (const ulonglong2*)(h_sh + (r + 1) * HD + half * 64);
                ull a0 = 0ull, b0 = 0ull, a1 = 0ull, b1 = 0ull;
                #pragma unroll
                for (int q = 0; q < 16; q++) {
                    ulonglong2 x0 = hp0[q];
                    ulonglong2 x1 = hp1[q];
                    ffma2(a0, x0.x, wq[2 * q]);
                    ffma2(b0, x0.x, wq[32 + 2 * q]);
                    ffma2(a1, x1.x, wq[2 * q]);
                    ffma2(b1, x1.x, wq[32 + 2 * q]);
                    ffma2(a0, x0.y, wq[2 * q + 1]);
                    ffma2(b0, x0.y, wq[32 + 2 * q + 1]);
                    ffma2(a1, x1.y, wq[2 * q + 1]);
                    ffma2(b1, x1.y, wq[32 + 2 * q + 1]);
                }
                float2 pa0 = unpack2(a0), pb0 = unpack2(b0);
                float2 pa1 = unpack2(a1), pb1 = unpack2(b1);
                ghOut[r * GD + o]        = (pa0.x + pa0.y) + bo0;
                ghOut[r * GD + o2]       = (pb0.x + pb0.y) + bo1;
                ghOut[(r + 1) * GD + o]  = (pa1.x + pa1.y) + bo0;
                ghOut[(r + 1) * GD + o2] = (pb1.x + pb1.y) + bo1;
            }
        }
        cp_wait_all();
        __syncthreads();
        #pragma unroll 1
        for (int idx = tid; idx < rows * HD; idx += 384) {
            int r = idx >> 7, j = idx & 127;
            float gir = gi_sh[r * GD + j]       + bih_sh[j];
            float giz = gi_sh[r * GD + j + 128] + bih_sh[j + 128];
            float gin = gi_sh[r * GD + j + 256] + bih_sh[j + 256];
            float ghr = ghA[r * GD + j]       + ghB[r * GD + j];
            float ghz = ghA[r * GD + j + 128] + ghB[r * GD + j + 128];
            float ghn = ghA[r * GD + j + 256] + ghB[r * GD + j + 256];
            float rg = __fdividef(1.f, 1.f + __expf(-(gir + ghr)));
            float zg = __fdividef(1.f, 1.f + __expf(-(giz + ghz)));
            float a2 = gin + rg * ghn;
            float ng = 1.f - __fdividef(2.f, __expf(2.f * a2) + 1.f);
            float hprev = h_sh[idx];
            float hn = (1.f - zg) * ng + zg * hprev;
            h_sh[idx] = hn;
            if (WRITE_SEQ)
                hout[((size_t)(base + r) * TS + t) * HD + j] = hn;
            else if (t == TS - 1)
                hout[(size_t)(base + r) * HD + j] = hn;
        }
        __syncthreads();
        if (t + 1 < TS) {
            const float* src = gi + ((size_t)(base + pr) * TS + (t + 1)) * GD;
            if (pact) {
                #pragma unroll
                for (int i = 0; i < 8; i++) {
                    int f = pc + 12 * i;
                    cp16(gi_sh + pr * GD + f * 4, src + f * 4);
                }
            }
            cp_commit();
        }
    }
}

// ---------------- small helpers --------------------------------------------
__global__ void k_zero(float* p, int n) {
    int i = blockIdx.x * blockDim.x + threadIdx.x;
    if (i < n) p[i] = 0.f;
}

// row L2-normalize; also emit bf16 hi/lo split of the normalized row
__global__ void k_rownorm(const float* __restrict__ src, float* __restrict__ dst,
                          bf16* __restrict__ hi, bf16* __restrict__ lo)
{
    int row = blockIdx.x * 8 + (threadIdx.x >> 5);
    int lane = threadIdx.x & 31;
    const float4* s4 = (const float4*)(src + (size_t)row * HD);
    float4 v = s4[lane];
    float ss = v.x*v.x + v.y*v.y + v.z*v.z + v.w*v.w;
    #pragma unroll
    for (int off = 16; off; off >>= 1) ss += __shfl_xor_sync(0xffffffffu, ss, off);
    float n = sqrtf(ss);
    float inv = (n > 0.f) ? 1.f / n : 0.f;
    float4 r = make_float4(v.x*inv, v.y*inv, v.z*inv, v.w*inv);
    ((float4*)(dst + (size_t)row * HD))[lane] = r;
    float rv[4] = {r.x, r.y, r.z, r.w};
    bf16 hb[4], lb[4];
    #pragma unroll
    for (int q = 0; q < 4; q++) {
        bf16 h = __float2bfloat16(rv[q]);
        hb[q] = h;
        lb[q] = __float2bfloat16(rv[q] - __bfloat162float(h));
    }
    *(uint2*)(hi + (size_t)row * HD + lane * 4) = *(uint2*)hb;
    *(uint2*)(lo + (size_t)row * HD + lane * 4) = *(uint2*)lb;
}

// cf2 = cf / colZ (row-wise), emitted as bf16 hi/lo
__global__ void k_cfscale(const float* __restrict__ cf,
                          const float* __restrict__ colZ,
                          bf16* __restrict__ hi, bf16* __restrict__ lo)
{
    int row = blockIdx.x * 8 + (threadIdx.x >> 5);
    int lane = threadIdx.x & 31;
    float rz = __fdividef(1.f, colZ[row]);
    float4 v = ((const float4*)(cf + (size_t)row * HD))[lane];
    float rv[4] = {v.x * rz, v.y * rz, v.z * rz, v.w * rz};
    bf16 hb[4], lb[4];
    #pragma unroll
    for (int q = 0; q < 4; q++) {
        bf16 h = __float2bfloat16(rv[q]);
        hb[q] = h;
        lb[q] = __float2bfloat16(rv[q] - __bfloat162float(h));
    }
    *(uint2*)(hi + (size_t)row * HD + lane * 4) = *(uint2*)hb;
    *(uint2*)(lo + (size_t)row * HD + lane * 4) = *(uint2*)lb;
}

// top-K=20 per row of |sim| (diag excluded), jax-stable ties (lowest index).
__global__ __launch_bounds__(256) void k_topk(
    const float* __restrict__ sim, int* __restrict__ tidx,
    float* __restrict__ tval, float* __restrict__ colsum)
{
    int i = blockIdx.x;
    __shared__ float sabs[NS];
    __shared__ float segv[128];
    __shared__ int   segi[128];
    __shared__ float bcv[4];
    __shared__ int   bci[4];
    const int tid = threadIdx.x;
    const float* row = sim + (size_t)i * NS;

    for (int c4 = tid; c4 < NS / 4; c4 += 256) {
        float4 v = *(const float4*)(row + c4 * 4);
        float4 a = make_float4(fabsf(v.x), fabsf(v.y), fabsf(v.z), fabsf(v.w));
        *(float4*)&sabs[c4 * 4] = a;
    }
    __syncthreads();
    if (tid == 0) sabs[i] = -1.f;
    __syncthreads();

    if (tid < 128) {
        float bv = -2.f; int bi = tid * 32;
        #pragma unroll 4
        for (int j = 0; j < 32; j++) {
            float v = sabs[tid * 32 + j];
            if (v > bv) { bv = v; bi = tid * 32 + j; }
        }
        segv[tid] = bv; segi[tid] = bi;
    }
    __syncthreads();

    for (int k = 0; k < NK; k++) {
        if (tid < 128) {
            float bv = segv[tid]; int bi = segi[tid];
            #pragma unroll
            for (int off = 16; off; off >>= 1) {
                float ov = __shfl_down_sync(0xffffffffu, bv, off);
                int   oi = __shfl_down_sync(0xffffffffu, bi, off);
                if (ov > bv || (ov == bv && oi < bi)) { bv = ov; bi = oi; }
            }
            if ((tid & 31) == 0) { bcv[tid >> 5] = bv; bci[tid >> 5] = bi; }
        }
        __syncthreads();
        if (tid < 32) {
            int bi = 0;
            if (tid == 0) {
                float bv = bcv[0]; bi = bci[0];
                #pragma unroll
                for (int w = 1; w < 4; w++)
                    if (bcv[w] > bv || (bcv[w] == bv && bci[w] < bi)) {
                        bv = bcv[w]; bi = bci[w];
                    }
                tidx[i * NK + k] = bi;
                float sv = row[bi];
                tval[i * NK + k] = sv;
                atomicAdd(&colsum[bi], sv);
                sabs[bi] = -2.f;
            }
            bi = __shfl_sync(0xffffffffu, bi, 0);
            __syncwarp();
            int s = bi >> 5;
            int idx = s * 32 + tid;
            float bv2 = sabs[idx]; int bi2 = idx;
            #pragma unroll
            for (int off = 16; off; off >>= 1) {
                float ov = __shfl_down_sync(0xffffffffu, bv2, off);
                int   oi = __shfl_down_sync(0xffffffffu, bi2, off);
                if (ov > bv2 || (ov == bv2 && oi < bi2)) { bv2 = ov; bi2 = oi; }
            }
            if (tid == 0) { segv[s] = bv2; segi[s] = bi2; }
        }
        __syncthreads();
    }
}

__global__ void k_scatter(const int* __restrict__ tidx, const float* __restrict__ tval,
                          const float* __restrict__ g, float* __restrict__ concept)
{
    int i = blockIdx.x, d = threadIdx.x;
    float gv = g[(size_t)i * HD + d];
    #pragma unroll
    for (int k = 0; k < NK; k++) {
        int c = __ldg(&tidx[i * NK + k]);
        float v = __ldg(&tval[i * NK + k]);
        atomicAdd(&concept[(size_t)c * HD + d], v * gv);
    }
}

__global__ void k_diag_valid(const float* __restrict__ colsum, const float* __restrict__ sim,
                             const float* __restrict__ g, float* __restrict__ concept,
                             float* __restrict__ valid)
{
    int j = blockIdx.x, t = threadIdx.x;
    float cs = colsum[j];
    float v = concept[(size_t)j * HD + t];
    if (cs != 0.f) {
        float dg = sim[(size_t)j * NS + j];
        v += dg * g[(size_t)j * HD + t];
        concept[(size_t)j * HD + t] = v;
    }
    float s = v;
    #pragma unroll
    for (int off = 16; off; off >>= 1) s += __shfl_xor_sync(0xffffffffu, s, off);
    __shared__ float ws[4];
    if ((t & 31) == 0) ws[t >> 5] = s;
    __syncthreads();
    if (t == 0) {
        float tot = ws[0] + ws[1] + ws[2] + ws[3];
        valid[j] = (tot != 0.f) ? 1.f : 0.f;
    }
}

__global__ void k_final(const float* __restrict__ fore, const float* __restrict__ indi,
                        const float* __restrict__ Wout, const float* __restrict__ bout,
                        float* __restrict__ out)
{
    int row = blockIdx.x * 8 + (threadIdx.x >> 5);
    int lane = threadIdx.x & 31;
    float4 a = ((const float4*)(fore + (size_t)row * HD))[lane];
    float4 b = ((const float4*)(indi + (size_t)row * HD))[lane];
    float4 w = ((const float4*)Wout)[lane];
    float s = (a.x+b.x)*w.x + (a.y+b.y)*w.y + (a.z+b.z)*w.z + (a.w+b.w)*w.w;
    #pragma unroll
    for (int off = 16; off; off >>= 1) s += __shfl_xor_sync(0xffffffffu, s, off);
    if (lane == 0) out[row] = s + bout[0];
}

// ---------------- driver -----------------------------------------------------
extern "C" void kernel_launch(void* const* d_in, const int* in_sizes, int n_in,
                              void* d_out, int out_size)
{
    const float* x     = (const float*)d_in[0];
    const float* Wih0  = (const float*)d_in[1];
    const float* Whh0  = (const float*)d_in[2];
    const float* bih0  = (const float*)d_in[3];
    const float* bhh0  = (const float*)d_in[4];
    const float* Wih1  = (const float*)d_in[5];
    const float* Whh1  = (const float*)d_in[6];
    const float* bih1  = (const float*)d_in[7];
    const float* bhh1  = (const float*)d_in[8];
    const float* W_hc  = (const float*)d_in[9];
    const float* b_hc  = (const float*)d_in[10];
    const float* W_hs  = (const float*)d_in[11];
    const float* b_hs  = (const float*)d_in[12];
    const float* W_fore= (const float*)d_in[13];
    const float* b_fore= (const float*)d_in[14];
    const float* W_back= (const float*)d_in[15];
    const float* b_back= (const float*)d_in[16];
    const float* W_indi= (const float*)d_in[17];
    const float* b_indi= (const float*)d_in[18];
    const float* W_out = (const float*)d_in[19];
    const float* b_out = (const float*)d_in[20];
    float* out = (float*)d_out;

    float *gi, *h0, *g, *gn, *sim, *colsum, *colZ, *valid, *concept;
    float *cf, *cfn, *hs, *t1, *t2, *t3, *t4, *tval;
    int* tidx;
    bf16 *w0hi, *w0lo, *whi, *wlo, *gnhi, *gnlo, *cfnhi, *cfnlo, *cf2hi, *cf2lo;
    cudaGetSymbolAddress((void**)&gi,      d_gi);
    cudaGetSymbolAddress((void**)&h0,      d_h0);
    cudaGetSymbolAddress((void**)&g,       d_g);
    cudaGetSymbolAddress((void**)&gn,      d_gn);
    cudaGetSymbolAddress((void**)&sim,     d_sim);
    cudaGetSymbolAddress((void**)&tidx,    d_tidx);
    cudaGetSymbolAddress((void**)&tval,    d_tval);
    cudaGetSymbolAddress((void**)&colsum,  d_colsum);
    cudaGetSymbolAddress((void**)&colZ,    d_colZ);
    cudaGetSymbolAddress((void**)&valid,   d_valid);
    cudaGetSymbolAddress((void**)&concept, d_concept);
    cudaGetSymbolAddress((void**)&cf,      d_cf);
    cudaGetSymbolAddress((void**)&cfn,     d_cfn);
    cudaGetSymbolAddress((void**)&hs,      d_hsb);
    cudaGetSymbolAddress((void**)&t1,      d_t1);
    cudaGetSymbolAddress((void**)&t2,      d_t2);
    cudaGetSymbolAddress((void**)&t3,      d_t3);
    cudaGetSymbolAddress((void**)&t4,      d_t4);
    cudaGetSymbolAddress((void**)&w0hi,    d_W0hi);
    cudaGetSymbolAddress((void**)&w0lo,    d_W0lo);
    cudaGetSymbolAddress((void**)&whi,     d_Whi);
    cudaGetSymbolAddress((void**)&wlo,     d_Wlo);
    cudaGetSymbolAddress((void**)&gnhi,    d_gnhi);
    cudaGetSymbolAddress((void**)&gnlo,    d_gnlo);
    cudaGetSymbolAddress((void**)&cfnhi,   d_cfnhi);
    cudaGetSymbolAddress((void**)&cfnlo,   d_cfnlo);
    cudaGetSymbolAddress((void**)&cf2hi,   d_cf2hi);
    cudaGetSymbolAddress((void**)&cf2lo,   d_cf2lo);

    // h 28*128 + ghA/ghB 2*28*384 + gi 28*384 floats = 143360 B
    const int GRU_SMEM = (GRROWS * HD + 3 * GRROWS * GD) * 4;
    cudaFuncSetAttribute((const void*)k_gru<true>,
                         cudaFuncAttributeMaxDynamicSharedMemorySize, GRU_SMEM);
    cudaFuncSetAttribute((const void*)k_gru<false>,
                         cudaFuncAttributeMaxDynamicSharedMemorySize, GRU_SMEM);

    const int MT = NS * TS;         // 262144
    const int GRU_GRID = (NS + GRROWS - 1) / GRROWS;  // 147

    // Launch order: gru0 is our 4th launch so ncu (-s 5 -c 1, one harness
    // pre-launch) captures the GRU kernel.
    // #1 split both input-weight matrices (one launch)
    k_wsplit2<<<(GD * FI + GD * HD + 255) / 256, 256>>>(
        Wih0, w0hi, w0lo, GD * FI, Wih1, whi, wlo, GD * HD);
    // #2 gi0 = x @ Wih0^T via wmma bf16x3 (K=32, 128x128 tile)
    k_wmma_nt<false><<<dim3(GD / 128, MT / 128), 256>>>(
        x, w0hi, w0lo, nullptr, gi, GD, FI);
    // #3 zero colsum
    k_zero<<<(NS + 255) / 256, 256>>>(colsum, NS);
    // #4 GRU layer 0 (writes full sequence)  <- ncu capture target
    k_gru<true><<<GRU_GRID, 384, GRU_SMEM>>>(gi, Whh0, bhh0, bih0, h0);
    // gi1 = h0 @ Wih1^T via wmma bf16x3 (K=128, 128x128 tile)
    k_wmma_nt<false><<<dim3(GD / 128, MT / 128), 256>>>(
        h0, whi, wlo, nullptr, gi, GD, HD);
    // GRU layer 1 (writes final hidden only -> g)
    k_gru<false><<<GRU_GRID, 384, GRU_SMEM>>>(gi, Whh1, bhh1, bih1, g);

    // zeros for later accumulators
    k_zero<<<(NS * HD + 255) / 256, 256>>>(concept, NS * HD);
    k_zero<<<(NS + 255) / 256, 256>>>(colZ, NS);

    // normalized g (fp32 + bf16 hi/lo); sim = gn @ gn^T (128x128 tile)
    k_rownorm<<<NS / 8, 256>>>(g, gn, gnhi, gnlo);
    k_wmma_nt<false><<<dim3(NS / 128, NS / 128), 256>>>(
        gn, gnhi, gnlo, nullptr, sim, NS, HD);

    // top-K selection + concept aggregation
    k_topk<<<NS, 256>>>(sim, tidx, tval, colsum);
    k_scatter<<<NS, 128>>>(tidx, tval, g, concept);
    k_diag_valid<<<NS, 128>>>(colsum, sim, g, concept, valid);

    // cf = lrelu(concept @ W_hc^T + b_hc) * valid
    k_gemm64<true, false><<<dim3(HD / 64, NS / 64), 256>>>(
        concept, W_hc, b_hc, valid, nullptr, cf, NS, HD, HD);
    k_rownorm<<<NS / 8, 256>>>(cf, cfn, cfnhi, cfnlo);

    // E = exp(gn @ cfn^T) with fused column sums (128x128 tile)
    k_wmma_nt<true><<<dim3(NS / 128, NS / 128), 256>>>(
        gn, cfnhi, cfnlo, colZ, sim, NS, HD);

    // cf2 = cf / colZ (bf16 hi/lo); t1 = E @ cf2 (wmma, split-K=8) + reduce
    k_cfscale<<<NS / 8, 256>>>(cf, colZ, cf2hi, cf2lo);
    k_wmma_nn<<<dim3(HD / 64, NS / 128, 8), 256>>>(
        sim, cf2hi, cf2lo, gi, NS, NS, NS / 8);
    k_reduce<<<(NS * HD / 4 + 255) / 256, 256>>>(gi, t1, 8, NS * HD / 4);

    // hs = lrelu(t1 @ W_hs^T + b_hs)
    k_gemm64<true, false><<<dim3(HD / 64, NS / 64), 256>>>(
        t1, W_hs, b_hs, nullptr, nullptr, hs, NS, HD, HD);

    // fused: t2 = lrelu(hs@W_fore^T+b_fore); t3 = g - lrelu(hs@W_back^T+b_back)
    k_gemm64_dual<<<dim3(HD / 64, NS / 64), 256>>>(
        hs, W_fore, b_fore, W_back, b_back, g, t2, t3, NS, HD, HD);
    // t4 = lrelu(t3 @ W_indi^T + b_indi)
    k_gemm64<true, false><<<dim3(HD / 64, NS / 64), 256>>>(
        t3, W_indi, b_indi, nullptr, nullptr, t4, NS, HD, HD);
    k_final<<<NS / 8, 256>>>(t2, t4, W_out, b_out, out);
}